// round 4
// baseline (speedup 1.0000x reference)
#include <cuda_runtime.h>
#include <cuda_fp16.h>
#include <stdint.h>
#include <math.h>

#define DD 512
#define BATCH 8
#define SEQ 2048
#define MTOT (BATCH * SEQ)   // 16384

#define TM 128
#define TN 256
#define BKK 64
#define NTH 256

#define STG_BYTES 49152           // A tile 16KB + B tile 32KB
#define OFF_B 16384
#define NSTG 3
#define SMEM_TOTAL (NSTG * STG_BYTES)   // 147456

// ---------------- scratch (device globals; no allocation) ----------------
__device__ __align__(1024) __half g_ITh[MTOT * DD];
__device__ __align__(1024) __half g_ISh[MTOT * DD];
__device__ __align__(1024) __half g_Wqh[4 * DD * DD];
__device__ __align__(1024) __half g_Wkh[4 * DD * DD];
__device__ __align__(1024) __half g_Wvh[4 * DD * DD];
__device__ __align__(1024) __half g_Qh[MTOT * DD];
__device__ __align__(1024) __half g_Kh[MTOT * DD];
__device__ __align__(1024) __half g_Vth[MTOT * DD];    // [feature][token] transposed
__device__ __align__(1024) __half g_S[(size_t)BATCH * SEQ * SEQ];
__device__ __align__(1024) __half g_P[(size_t)BATCH * SEQ * SEQ];
__device__ __align__(1024) float  g_A[MTOT * DD];
__device__ __align__(1024) float  g_C[MTOT * DD];
__device__ __align__(1024) __half g_Ah[MTOT * DD];
__device__ __align__(1024) __half g_Ch[MTOT * DD];

// ---------------- helpers ----------------
__device__ __forceinline__ uint32_t s2u(const void* p) {
    uint32_t a;
    asm("{ .reg .u64 t; cvta.to.shared.u64 t, %1; cvt.u32.u64 %0, t; }" : "=r"(a) : "l"(p));
    return a;
}
__device__ __forceinline__ void cp16(uint32_t dst, const void* src) {
    asm volatile("cp.async.cg.shared.global [%0], [%1], 16;" :: "r"(dst), "l"(src));
}
__device__ __forceinline__ void cp_commit() { asm volatile("cp.async.commit_group;" ::: "memory"); }
template <int N> __device__ __forceinline__ void cp_wait() {
    asm volatile("cp.async.wait_group %0;" :: "n"(N) : "memory");
}
__device__ __forceinline__ void ldsm4(uint32_t* d, uint32_t addr) {
    asm volatile("ldmatrix.sync.aligned.m8n8.x4.shared.b16 {%0,%1,%2,%3}, [%4];"
                 : "=r"(d[0]), "=r"(d[1]), "=r"(d[2]), "=r"(d[3]) : "r"(addr));
}
__device__ __forceinline__ void mma16816(float* c, const uint32_t* a, uint32_t b0, uint32_t b1) {
    asm volatile(
        "mma.sync.aligned.m16n8k16.row.col.f32.f16.f16.f32 "
        "{%0,%1,%2,%3},{%4,%5,%6,%7},{%8,%9},{%0,%1,%2,%3};"
        : "+f"(c[0]), "+f"(c[1]), "+f"(c[2]), "+f"(c[3])
        : "r"(a[0]), "r"(a[1]), "r"(a[2]), "r"(a[3]), "r"(b0), "r"(b1));
}

// ---------------------------------------------------------------------------
// NT GEMM: D[m,n] = sum_k A[m,k] * B[n,k]   (both fp16 K-contiguous), fp32 acc
// CTA tile 128x256, 8 warps (2m x 4n), warp tile 64x64, 3-stage cp.async.
// ---------------------------------------------------------------------------
enum { MODE_QK = 0, MODE_VT = 1, MODE_SC = 2, MODE_PV = 3, MODE_FIN = 4 };

template <int MODE>
__global__ __launch_bounds__(NTH, 1)
void hgemm(const __half* __restrict__ A, const __half* __restrict__ B,
           void* __restrict__ out, const float* __restrict__ X,
           int ldA, int ldB, int ldC, int K,
           long long strA, long long strB, long long strC,
           float alpha, int accflag)
{
    extern __shared__ __align__(16) char smem[];
    const uint32_t sbase = s2u(smem);
    const int tid  = threadIdx.x;
    const int lane = tid & 31;
    const int warp = tid >> 5;
    const int wm = warp & 1;          // 2 warps along m (64 each)
    const int wn = warp >> 1;         // 4 warps along n (64 each)
    const int z  = blockIdx.z;
    const int m0 = blockIdx.y * TM;
    const int n0 = blockIdx.x * TN;

    const __half* Ap = A + (size_t)z * strA;
    const __half* Bp = B + (size_t)z * strB;

    float acc[4][8][4];
    #pragma unroll
    for (int i = 0; i < 4; i++)
        #pragma unroll
        for (int j = 0; j < 8; j++)
            #pragma unroll
            for (int e = 0; e < 4; e++) acc[i][j][e] = 0.f;

    const int nK = K / BKK;

    auto load_stage = [&](int ck, int stg) {
        const int k0 = ck * BKK;
        const uint32_t sb = sbase + stg * STG_BYTES;
        #pragma unroll
        for (int t = 0; t < 4; t++) {               // A: 128 rows x 128B
            int id = tid + t * NTH;
            int r = id >> 3, c = id & 7;
            cp16(sb + r * 128 + (((c ^ (r & 7)) & 7) << 4),
                 Ap + (size_t)(m0 + r) * ldA + k0 + c * 8);
        }
        #pragma unroll
        for (int t = 0; t < 8; t++) {               // B: 256 rows x 128B
            int id = tid + t * NTH;
            int r = id >> 3, c = id & 7;
            cp16(sb + OFF_B + r * 128 + (((c ^ (r & 7)) & 7) << 4),
                 Bp + (size_t)(n0 + r) * ldB + k0 + c * 8);
        }
        cp_commit();
    };

    load_stage(0, 0);
    if (nK > 1) load_stage(1, 1);

    for (int i = 0; i < nK; i++) {
        if (i + 1 < nK) cp_wait<1>(); else cp_wait<0>();
        __syncthreads();
        if (i + 2 < nK) load_stage(i + 2, (i + 2) % 3);

        const uint32_t sA = sbase + (i % 3) * STG_BYTES;
        const uint32_t sB = sA + OFF_B;

        #pragma unroll
        for (int s = 0; s < 4; s++) {
            uint32_t af[4][4];
            #pragma unroll
            for (int im = 0; im < 4; im++) {
                int row = wm * 64 + im * 16 + (lane & 15);
                int ch  = 2 * s + (lane >> 4);
                ldsm4(af[im], sA + row * 128 + (((ch ^ (row & 7)) & 7) << 4));
            }
            uint32_t bf[4][4];
            #pragma unroll
            for (int j2 = 0; j2 < 4; j2++) {
                int row = wn * 64 + j2 * 16 + ((lane >> 4) << 3) + (lane & 7);
                int ch  = 2 * s + ((lane >> 3) & 1);
                ldsm4(bf[j2], sB + row * 128 + (((ch ^ (row & 7)) & 7) << 4));
            }
            #pragma unroll
            for (int im = 0; im < 4; im++)
                #pragma unroll
                for (int jn = 0; jn < 8; jn++)
                    mma16816(acc[im][jn], af[im], bf[jn >> 1][(jn & 1) * 2],
                             bf[jn >> 1][(jn & 1) * 2 + 1]);
        }
        __syncthreads();
    }

    // ---------------- epilogue ----------------
    const int lm = lane >> 2;
    const int ln = (lane & 3) * 2;

    if (MODE == MODE_VT) {
        // stage transposed tile in smem: st[n_local][m_local], stride 136 halves
        __half* st = (__half*)smem;
        #pragma unroll
        for (int im = 0; im < 4; im++) {
            int ml = wm * 64 + im * 16 + lm;
            #pragma unroll
            for (int jn = 0; jn < 8; jn++) {
                int nl = wn * 64 + jn * 8 + ln;
                float b0 = X[n0 + nl], b1 = X[n0 + nl + 1];
                st[nl * 136 + ml]           = __float2half(acc[im][jn][0] + b0);
                st[(nl + 1) * 136 + ml]     = __float2half(acc[im][jn][1] + b1);
                st[nl * 136 + ml + 8]       = __float2half(acc[im][jn][2] + b0);
                st[(nl + 1) * 136 + ml + 8] = __float2half(acc[im][jn][3] + b1);
            }
        }
        __syncthreads();
        __half* O = (__half*)out;
        #pragma unroll
        for (int t = 0; t < 16; t++) {
            int idx = tid + t * NTH;             // 4096 chunks of 16B (256 rows x 16)
            int r = idx >> 4, sgl = idx & 15;
            uint4 v = *(const uint4*)(st + r * 136 + sgl * 8);
            *(uint4*)(O + (size_t)(n0 + r) * ldC + m0 + sgl * 8) = v;
        }
        return;
    }

    #pragma unroll
    for (int im = 0; im < 4; im++) {
        int r0 = m0 + wm * 64 + im * 16 + lm;
        int r1 = r0 + 8;
        #pragma unroll
        for (int jn = 0; jn < 8; jn++) {
            int c = n0 + wn * 64 + jn * 8 + ln;
            float v0 = acc[im][jn][0], v1 = acc[im][jn][1];
            float v2 = acc[im][jn][2], v3 = acc[im][jn][3];
            if (MODE == MODE_QK) {
                __half* O = (__half*)out;
                float b0 = X[c], b1 = X[c + 1];
                *(__half2*)(O + (size_t)r0 * ldC + c) = __floats2half2_rn(v0 + b0, v1 + b1);
                *(__half2*)(O + (size_t)r1 * ldC + c) = __floats2half2_rn(v2 + b0, v3 + b1);
            } else if (MODE == MODE_SC) {
                __half* O = (__half*)out + (size_t)z * strC;
                *(__half2*)(O + (size_t)r0 * ldC + c) = __floats2half2_rn(v0 * alpha, v1 * alpha);
                *(__half2*)(O + (size_t)r1 * ldC + c) = __floats2half2_rn(v2 * alpha, v3 * alpha);
            } else if (MODE == MODE_PV) {
                float* O = (float*)out + (size_t)z * strC;
                size_t o0 = (size_t)r0 * ldC + c, o1 = (size_t)r1 * ldC + c;
                if (accflag) {
                    float2 p0 = *(float2*)(O + o0), p1 = *(float2*)(O + o1);
                    v0 += p0.x; v1 += p0.y; v2 += p1.x; v3 += p1.y;
                }
                *(float2*)(O + o0) = make_float2(v0, v1);
                *(float2*)(O + o1) = make_float2(v2, v3);
            } else {  // MODE_FIN
                float* O = (float*)out + (size_t)z * strC;
                const float* Xz = X + (size_t)z * strC;
                size_t o0 = (size_t)r0 * ldC + c, o1 = (size_t)r1 * ldC + c;
                float2 p0 = *(const float2*)(Xz + o0), p1 = *(const float2*)(Xz + o1);
                *(float2*)(O + o0) = make_float2(v0 + p0.x, v1 + p0.y);
                *(float2*)(O + o1) = make_float2(v2 + p1.x, v3 + p1.y);
            }
        }
    }
}

// ---------------------------------------------------------------------------
// fp32 -> fp16 convert
// ---------------------------------------------------------------------------
__global__ __launch_bounds__(256)
void tohalf_kernel(const float* __restrict__ src, __half* __restrict__ dst, int n4)
{
    int idx = blockIdx.x * blockDim.x + threadIdx.x;
    int stride = gridDim.x * blockDim.x;
    const float4* s4 = (const float4*)src;
    __half2* d2 = (__half2*)dst;
    for (int i = idx; i < n4; i += stride) {
        float4 v = s4[i];
        d2[i * 2]     = __floats2half2_rn(v.x, v.y);
        d2[i * 2 + 1] = __floats2half2_rn(v.z, v.w);
    }
}

// ---------------------------------------------------------------------------
// Row softmax over 2048 fp16 cols -> fp16 probabilities
// ---------------------------------------------------------------------------
__global__ __launch_bounds__(256)
void softmax_kernel(const __half* __restrict__ S, __half* __restrict__ P)
{
    const size_t base = (size_t)blockIdx.x * SEQ;
    const int tid = threadIdx.x;

    float vals[8];
    float m = -INFINITY;
    #pragma unroll
    for (int i = 0; i < 4; i++) {
        __half2 h = *(const __half2*)(S + base + tid * 2 + i * 512);
        vals[i * 2]     = __half2float(h.x);
        vals[i * 2 + 1] = __half2float(h.y);
        m = fmaxf(m, fmaxf(vals[i * 2], vals[i * 2 + 1]));
    }
    __shared__ float red[256];
    red[tid] = m;
    __syncthreads();
    #pragma unroll
    for (int s = 128; s > 0; s >>= 1) {
        if (tid < s) red[tid] = fmaxf(red[tid], red[tid + s]);
        __syncthreads();
    }
    m = red[0];
    __syncthreads();

    float sum = 0.f;
    #pragma unroll
    for (int i = 0; i < 8; i++) {
        vals[i] = expf(vals[i] - m);
        sum += vals[i];
    }
    red[tid] = sum;
    __syncthreads();
    #pragma unroll
    for (int s = 128; s > 0; s >>= 1) {
        if (tid < s) red[tid] += red[tid + s];
        __syncthreads();
    }
    float inv = 1.0f / red[0];

    #pragma unroll
    for (int i = 0; i < 4; i++) {
        *(__half2*)(P + base + tid * 2 + i * 512) =
            __floats2half2_rn(vals[i * 2] * inv, vals[i * 2 + 1] * inv);
    }
}

// ---------------------------------------------------------------------------
extern "C" void kernel_launch(void* const* d_in, const int* in_sizes, int n_in,
                              void* d_out, int out_size)
{
    const float* Itime   = (const float*)d_in[0];
    const float* Ispace  = (const float*)d_in[1];
    const float* xorigin = (const float*)d_in[2];
    const float* Wq      = (const float*)d_in[3];
    const float* bq      = (const float*)d_in[4];
    const float* Wk      = (const float*)d_in[5];
    const float* bk      = (const float*)d_in[6];
    const float* Wv      = (const float*)d_in[7];
    const float* bv      = (const float*)d_in[8];
    float* out = (float*)d_out;

    __half *ITh, *ISh, *Wqh, *Wkh, *Wvh, *Qh, *Kh, *Vth, *Sh, *Ph, *Ah, *Ch;
    float *Af, *Cf;
    cudaGetSymbolAddress((void**)&ITh, g_ITh);
    cudaGetSymbolAddress((void**)&ISh, g_ISh);
    cudaGetSymbolAddress((void**)&Wqh, g_Wqh);
    cudaGetSymbolAddress((void**)&Wkh, g_Wkh);
    cudaGetSymbolAddress((void**)&Wvh, g_Wvh);
    cudaGetSymbolAddress((void**)&Qh,  g_Qh);
    cudaGetSymbolAddress((void**)&Kh,  g_Kh);
    cudaGetSymbolAddress((void**)&Vth, g_Vth);
    cudaGetSymbolAddress((void**)&Sh,  g_S);
    cudaGetSymbolAddress((void**)&Ph,  g_P);
    cudaGetSymbolAddress((void**)&Ah,  g_Ah);
    cudaGetSymbolAddress((void**)&Ch,  g_Ch);
    cudaGetSymbolAddress((void**)&Af,  g_A);
    cudaGetSymbolAddress((void**)&Cf,  g_C);

    cudaFuncSetAttribute(hgemm<MODE_QK>,  cudaFuncAttributeMaxDynamicSharedMemorySize, SMEM_TOTAL);
    cudaFuncSetAttribute(hgemm<MODE_VT>,  cudaFuncAttributeMaxDynamicSharedMemorySize, SMEM_TOTAL);
    cudaFuncSetAttribute(hgemm<MODE_SC>,  cudaFuncAttributeMaxDynamicSharedMemorySize, SMEM_TOTAL);
    cudaFuncSetAttribute(hgemm<MODE_PV>,  cudaFuncAttributeMaxDynamicSharedMemorySize, SMEM_TOTAL);
    cudaFuncSetAttribute(hgemm<MODE_FIN>, cudaFuncAttributeMaxDynamicSharedMemorySize, SMEM_TOTAL);

    const float scale = 0.044194173824159216f;  // 1/sqrt(512)
    const long long sQKV = (long long)SEQ * DD;
    const long long sS   = (long long)SEQ * SEQ;

    // input converts
    tohalf_kernel<<<2048, 256>>>(Itime,  ITh, MTOT * DD / 4);
    tohalf_kernel<<<2048, 256>>>(Ispace, ISh, MTOT * DD / 4);
    tohalf_kernel<<<512,  256>>>(Wq, Wqh, 4 * DD * DD / 4);
    tohalf_kernel<<<512,  256>>>(Wk, Wkh, 4 * DD * DD / 4);
    tohalf_kernel<<<512,  256>>>(Wv, Wvh, 4 * DD * DD / 4);

    struct Blk { const __half *q, *kv; int w; float* F; int acc; };
    const Blk blks[4] = {
        { ITh, ITh, 0, Af, 0 },   // FTT
        { ITh, ISh, 2, Af, 1 },   // FTS
        { ISh, ISh, 1, Cf, 0 },   // FSS
        { ISh, ITh, 3, Cf, 1 },   // FST
    };

    for (int i = 0; i < 4; i++) {
        const Blk& b = blks[i];
        const size_t wo = (size_t)b.w * DD * DD;

        dim3 gproj(DD / TN, MTOT / TM, 1);
        hgemm<MODE_QK><<<gproj, NTH, SMEM_TOTAL>>>(
            b.q,  Wqh + wo, Qh, bq + b.w * DD,
            DD, DD, DD, DD, 0, 0, 0, 1.0f, 0);
        hgemm<MODE_QK><<<gproj, NTH, SMEM_TOTAL>>>(
            b.kv, Wkh + wo, Kh, bk + b.w * DD,
            DD, DD, DD, DD, 0, 0, 0, 1.0f, 0);
        hgemm<MODE_VT><<<gproj, NTH, SMEM_TOTAL>>>(
            b.kv, Wvh + wo, Vth, bv + b.w * DD,
            DD, DD, MTOT, DD, 0, 0, 0, 1.0f, 0);

        dim3 gsc(SEQ / TN, SEQ / TM, BATCH);
        hgemm<MODE_SC><<<gsc, NTH, SMEM_TOTAL>>>(
            Qh, Kh, Sh, nullptr,
            DD, DD, SEQ, DD, sQKV, sQKV, sS, scale, 0);

        softmax_kernel<<<MTOT, 256>>>(Sh, Ph);

        // F[z] (+)= P[z] @ Vt[z]^T : A = P (K-contig over keys), B = Vt (K-contig)
        dim3 gpv(DD / TN, SEQ / TM, BATCH);
        hgemm<MODE_PV><<<gpv, NTH, SMEM_TOTAL>>>(
            Ph, Vth, b.F, nullptr,
            SEQ, MTOT, DD, SEQ, sS, SEQ, sQKV, 1.0f, b.acc);
    }

    tohalf_kernel<<<2048, 256>>>(Af, Ah, MTOT * DD / 4);
    tohalf_kernel<<<2048, 256>>>(Cf, Ch, MTOT * DD / 4);

    dim3 gfin(SEQ / TN, SEQ / TM, BATCH);
    hgemm<MODE_FIN><<<gfin, NTH, SMEM_TOTAL>>>(
        Ah, Ch, out, xorigin,
        DD, DD, SEQ, DD, sQKV, sQKV, sS, 1.0f, 0);
}

// round 6
// speedup vs baseline: 1.2183x; 1.2183x over previous
#include <cuda_runtime.h>
#include <cuda_fp16.h>
#include <stdint.h>
#include <math.h>

#define DD 512
#define BATCH 8
#define SEQ 2048
#define MTOT (BATCH * SEQ)   // 16384

#define TM 128
#define TN 128
#define BKK 64
#define NTH 256

#define STG_BYTES 32768           // A tile 16KB + B tile 16KB
#define SMEM_TOTAL 65536          // 2 stages

// ---------------- scratch (device globals; no allocation) ----------------
__device__ __align__(1024) __half g_ITh[MTOT * DD];                       // 16MB
__device__ __align__(1024) __half g_ISh[MTOT * DD];                       // 16MB
__device__ __align__(1024) __half g_Wqh[4 * DD * DD];
__device__ __align__(1024) __half g_Wkh[4 * DD * DD];
__device__ __align__(1024) __half g_Wvh[4 * DD * DD];
__device__ __align__(1024) __half g_Qh[4 * MTOT * DD];                    // 64MB  [blk][batch][tok][feat]
__device__ __align__(1024) __half g_Kh[4 * MTOT * DD];                    // 64MB
__device__ __align__(1024) __half g_Vth[4 * DD * MTOT];                   // 64MB  [blk][feat][tok]
__device__ __align__(1024) __half g_S[(size_t)32 * SEQ * SEQ];            // 256MB [blk*8+batch][q][k]
__device__ __align__(1024) __half g_F[(size_t)4 * MTOT * DD];             // 64MB  [blk][batch][tok][feat]
__device__ __align__(1024) __half g_Ah[MTOT * DD];                        // 16MB
__device__ __align__(1024) __half g_Ch[MTOT * DD];                        // 16MB

// ---------------- helpers ----------------
__device__ __forceinline__ uint32_t s2u(const void* p) {
    uint32_t a;
    asm("{ .reg .u64 t; cvta.to.shared.u64 t, %1; cvt.u32.u64 %0, t; }" : "=r"(a) : "l"(p));
    return a;
}
__device__ __forceinline__ void cp16(uint32_t dst, const void* src) {
    asm volatile("cp.async.cg.shared.global [%0], [%1], 16;" :: "r"(dst), "l"(src));
}
__device__ __forceinline__ void cp_commit() { asm volatile("cp.async.commit_group;" ::: "memory"); }
template <int N> __device__ __forceinline__ void cp_wait() {
    asm volatile("cp.async.wait_group %0;" :: "n"(N) : "memory");
}
__device__ __forceinline__ void ldsm4(uint32_t* d, uint32_t addr) {
    asm volatile("ldmatrix.sync.aligned.m8n8.x4.shared.b16 {%0,%1,%2,%3}, [%4];"
                 : "=r"(d[0]), "=r"(d[1]), "=r"(d[2]), "=r"(d[3]) : "r"(addr));
}
__device__ __forceinline__ void mma16816(float* c, const uint32_t* a, uint32_t b0, uint32_t b1) {
    asm volatile(
        "mma.sync.aligned.m16n8k16.row.col.f32.f16.f16.f32 "
        "{%0,%1,%2,%3},{%4,%5,%6,%7},{%8,%9},{%0,%1,%2,%3};"
        : "+f"(c[0]), "+f"(c[1]), "+f"(c[2]), "+f"(c[3])
        : "r"(a[0]), "r"(a[1]), "r"(a[2]), "r"(a[3]), "r"(b0), "r"(b1));
}

// ---------------------------------------------------------------------------
// NT GEMM: D[m,n] = sum_k A[m,k] * B[n,k]  (fp16 in, fp32 acc)
// CTA 128x128, 8 warps (2m x 4n), warp tile 64x32, 2-stage cp.async.
// z-batched: zh = z>>3, zl = z&7; operand offsets via hi/lo strides.
// A operand selected from {A0, A1} by bit z of amask.
// ---------------------------------------------------------------------------
enum { MODE_QK = 0, MODE_VT = 1, MODE_SC = 2, MODE_PV = 3, MODE_FIN = 4 };

template <int MODE>
__global__ __launch_bounds__(NTH, 2)
void hgemm(const __half* __restrict__ A0, const __half* __restrict__ A1, uint32_t amask,
           const __half* __restrict__ B, void* __restrict__ out, const float* __restrict__ X,
           int ldA, int ldB, int ldC, int K,
           long long sAhi, long long sAlo, long long sBhi, long long sBlo,
           long long sChi, long long sClo, long long sXlo,
           float alpha)
{
    extern __shared__ __align__(16) char smem[];
    const uint32_t sbase = s2u(smem);
    const int tid  = threadIdx.x;
    const int lane = tid & 31;
    const int warp = tid >> 5;
    const int wm = warp & 1;
    const int wn = warp >> 1;
    const int z  = blockIdx.z;
    const int zh = z >> 3, zl = z & 7;
    const int m0 = blockIdx.y * TM;
    const int n0 = blockIdx.x * TN;

    const __half* Ap = (((amask >> z) & 1) ? A1 : A0) + zh * sAhi + zl * sAlo;
    const __half* Bp = B + zh * sBhi + zl * sBlo;
    const size_t  co = (size_t)(zh * sChi + zl * sClo);

    float acc[4][4][4];
    #pragma unroll
    for (int i = 0; i < 4; i++)
        #pragma unroll
        for (int j = 0; j < 4; j++)
            #pragma unroll
            for (int e = 0; e < 4; e++) acc[i][j][e] = 0.f;

    const int nK = K / BKK;

    auto load_stage = [&](int ck, int stg) {
        const int k0 = ck * BKK;
        const uint32_t sb = sbase + stg * STG_BYTES;
        #pragma unroll
        for (int t = 0; t < 4; t++) {               // A: 128 rows x 128B
            int id = tid + t * NTH;
            int r = id >> 3, c = id & 7;
            cp16(sb + r * 128 + (((c ^ (r & 7)) & 7) << 4),
                 Ap + (size_t)(m0 + r) * ldA + k0 + c * 8);
        }
        #pragma unroll
        for (int t = 0; t < 4; t++) {               // B: 128 rows x 128B
            int id = tid + t * NTH;
            int r = id >> 3, c = id & 7;
            cp16(sb + 16384 + r * 128 + (((c ^ (r & 7)) & 7) << 4),
                 Bp + (size_t)(n0 + r) * ldB + k0 + c * 8);
        }
        cp_commit();
    };

    load_stage(0, 0);

    for (int i = 0; i < nK; i++) {
        cp_wait<0>();
        __syncthreads();
        if (i + 1 < nK) load_stage(i + 1, (i + 1) & 1);

        const uint32_t sA = sbase + (i & 1) * STG_BYTES;
        const uint32_t sB = sA + 16384;

        #pragma unroll
        for (int s = 0; s < 4; s++) {
            uint32_t af[4][4];
            #pragma unroll
            for (int im = 0; im < 4; im++) {
                int row = wm * 64 + im * 16 + (lane & 15);
                int ch  = 2 * s + (lane >> 4);
                ldsm4(af[im], sA + row * 128 + (((ch ^ (row & 7)) & 7) << 4));
            }
            uint32_t bf[2][4];
            #pragma unroll
            for (int j2 = 0; j2 < 2; j2++) {
                int row = wn * 32 + j2 * 16 + ((lane >> 4) << 3) + (lane & 7);
                int ch  = 2 * s + ((lane >> 3) & 1);
                ldsm4(bf[j2], sB + row * 128 + (((ch ^ (row & 7)) & 7) << 4));
            }
            #pragma unroll
            for (int im = 0; im < 4; im++)
                #pragma unroll
                for (int jn = 0; jn < 4; jn++)
                    mma16816(acc[im][jn], af[im], bf[jn >> 1][(jn & 1) * 2],
                             bf[jn >> 1][(jn & 1) * 2 + 1]);
        }
        __syncthreads();
    }

    // ---------------- epilogue ----------------
    const int lm = lane >> 2;
    const int ln = (lane & 3) * 2;

    if (MODE == MODE_VT) {
        // transpose via smem: st[n_local][m_local], stride 136 halves
        __half* st = (__half*)smem;
        const float* Xp = X + zl * sXlo;
        #pragma unroll
        for (int im = 0; im < 4; im++) {
            int ml = wm * 64 + im * 16 + lm;
            #pragma unroll
            for (int jn = 0; jn < 4; jn++) {
                int nl = wn * 32 + jn * 8 + ln;
                float b0 = Xp[n0 + nl], b1 = Xp[n0 + nl + 1];
                st[nl * 136 + ml]           = __float2half(acc[im][jn][0] + b0);
                st[(nl + 1) * 136 + ml]     = __float2half(acc[im][jn][1] + b1);
                st[nl * 136 + ml + 8]       = __float2half(acc[im][jn][2] + b0);
                st[(nl + 1) * 136 + ml + 8] = __float2half(acc[im][jn][3] + b1);
            }
        }
        __syncthreads();
        __half* O = (__half*)out + co;
        #pragma unroll
        for (int t = 0; t < 8; t++) {
            int idx = tid + t * NTH;             // 2048 chunks of 16B
            int r = idx >> 4, sgl = idx & 15;
            uint4 v = *(const uint4*)(st + r * 136 + sgl * 8);
            *(uint4*)(O + (size_t)(n0 + r) * ldC + m0 + sgl * 8) = v;
        }
        return;
    }

    #pragma unroll
    for (int im = 0; im < 4; im++) {
        int r0 = m0 + wm * 64 + im * 16 + lm;
        int r1 = r0 + 8;
        #pragma unroll
        for (int jn = 0; jn < 4; jn++) {
            int c = n0 + wn * 32 + jn * 8 + ln;
            float v0 = acc[im][jn][0], v1 = acc[im][jn][1];
            float v2 = acc[im][jn][2], v3 = acc[im][jn][3];
            if (MODE == MODE_QK) {
                __half* O = (__half*)out + co;
                const float* Xp = X + zl * sXlo;
                float b0 = Xp[c], b1 = Xp[c + 1];
                *(__half2*)(O + (size_t)r0 * ldC + c) = __floats2half2_rn(v0 + b0, v1 + b1);
                *(__half2*)(O + (size_t)r1 * ldC + c) = __floats2half2_rn(v2 + b0, v3 + b1);
            } else if (MODE == MODE_SC) {
                __half* O = (__half*)out + co;
                *(__half2*)(O + (size_t)r0 * ldC + c) = __floats2half2_rn(v0 * alpha, v1 * alpha);
                *(__half2*)(O + (size_t)r1 * ldC + c) = __floats2half2_rn(v2 * alpha, v3 * alpha);
            } else if (MODE == MODE_PV) {
                __half* O = (__half*)out + co;
                *(__half2*)(O + (size_t)r0 * ldC + c) = __floats2half2_rn(v0, v1);
                *(__half2*)(O + (size_t)r1 * ldC + c) = __floats2half2_rn(v2, v3);
            } else {  // MODE_FIN
                float* O = (float*)out + co;
                const float* Xz = X + zl * sXlo;
                size_t o0 = (size_t)r0 * ldC + c, o1 = (size_t)r1 * ldC + c;
                float2 p0 = *(const float2*)(Xz + o0), p1 = *(const float2*)(Xz + o1);
                *(float2*)(O + o0) = make_float2(v0 + p0.x, v1 + p0.y);
                *(float2*)(O + o1) = make_float2(v2 + p1.x, v3 + p1.y);
            }
        }
    }
}

// ---------------------------------------------------------------------------
// fp32 -> fp16 convert
// ---------------------------------------------------------------------------
__global__ __launch_bounds__(256)
void tohalf_kernel(const float* __restrict__ src, __half* __restrict__ dst, int n4)
{
    int idx = blockIdx.x * blockDim.x + threadIdx.x;
    int stride = gridDim.x * blockDim.x;
    const float4* s4 = (const float4*)src;
    __half2* d2 = (__half2*)dst;
    for (int i = idx; i < n4; i += stride) {
        float4 v = s4[i];
        d2[i * 2]     = __floats2half2_rn(v.x, v.y);
        d2[i * 2 + 1] = __floats2half2_rn(v.z, v.w);
    }
}

// ---------------------------------------------------------------------------
// Ah = F[0] + F[2]  (FTT + FTS),   Ch = F[1] + F[3]  (FSS + FST)
// F is indexed by WEIGHT index: 0=FTT, 1=FSS, 2=FTS, 3=FST.
// ---------------------------------------------------------------------------
__global__ __launch_bounds__(256)
void fuse_kernel(const __half* __restrict__ F, __half* __restrict__ Ah,
                 __half* __restrict__ Ch, int n8)
{
    const size_t blk = (size_t)MTOT * DD;
    int idx = blockIdx.x * blockDim.x + threadIdx.x;
    int stride = gridDim.x * blockDim.x;
    const uint4* fTT = (const uint4*)F;
    const uint4* fSS = (const uint4*)(F + blk);
    const uint4* fTS = (const uint4*)(F + 2 * blk);
    const uint4* fST = (const uint4*)(F + 3 * blk);
    uint4* a4 = (uint4*)Ah;
    uint4* c4 = (uint4*)Ch;
    for (int i = idx; i < n8; i += stride) {
        uint4 x = fTT[i], y = fTS[i], r;
        ((__half2*)&r)[0] = __hadd2(((__half2*)&x)[0], ((__half2*)&y)[0]);
        ((__half2*)&r)[1] = __hadd2(((__half2*)&x)[1], ((__half2*)&y)[1]);
        ((__half2*)&r)[2] = __hadd2(((__half2*)&x)[2], ((__half2*)&y)[2]);
        ((__half2*)&r)[3] = __hadd2(((__half2*)&x)[3], ((__half2*)&y)[3]);
        a4[i] = r;
        x = fSS[i]; y = fST[i];
        ((__half2*)&r)[0] = __hadd2(((__half2*)&x)[0], ((__half2*)&y)[0]);
        ((__half2*)&r)[1] = __hadd2(((__half2*)&x)[1], ((__half2*)&y)[1]);
        ((__half2*)&r)[2] = __hadd2(((__half2*)&x)[2], ((__half2*)&y)[2]);
        ((__half2*)&r)[3] = __hadd2(((__half2*)&x)[3], ((__half2*)&y)[3]);
        c4[i] = r;
    }
}

// ---------------------------------------------------------------------------
// Row softmax over 2048 fp16 cols, in place
// ---------------------------------------------------------------------------
__global__ __launch_bounds__(256)
void softmax_kernel(__half* __restrict__ S)
{
    const size_t base = (size_t)blockIdx.x * SEQ;
    const int tid = threadIdx.x;

    float vals[8];
    float m = -INFINITY;
    #pragma unroll
    for (int i = 0; i < 4; i++) {
        __half2 h = *(const __half2*)(S + base + tid * 2 + i * 512);
        vals[i * 2]     = __half2float(h.x);
        vals[i * 2 + 1] = __half2float(h.y);
        m = fmaxf(m, fmaxf(vals[i * 2], vals[i * 2 + 1]));
    }
    __shared__ float red[256];
    red[tid] = m;
    __syncthreads();
    #pragma unroll
    for (int s = 128; s > 0; s >>= 1) {
        if (tid < s) red[tid] = fmaxf(red[tid], red[tid + s]);
        __syncthreads();
    }
    m = red[0];
    __syncthreads();

    float sum = 0.f;
    #pragma unroll
    for (int i = 0; i < 8; i++) {
        vals[i] = expf(vals[i] - m);
        sum += vals[i];
    }
    red[tid] = sum;
    __syncthreads();
    #pragma unroll
    for (int s = 128; s > 0; s >>= 1) {
        if (tid < s) red[tid] += red[tid + s];
        __syncthreads();
    }
    float inv = 1.0f / red[0];

    #pragma unroll
    for (int i = 0; i < 4; i++) {
        *(__half2*)(S + base + tid * 2 + i * 512) =
            __floats2half2_rn(vals[i * 2] * inv, vals[i * 2 + 1] * inv);
    }
}

// ---------------------------------------------------------------------------
extern "C" void kernel_launch(void* const* d_in, const int* in_sizes, int n_in,
                              void* d_out, int out_size)
{
    const float* Itime   = (const float*)d_in[0];
    const float* Ispace  = (const float*)d_in[1];
    const float* xorigin = (const float*)d_in[2];
    const float* Wq      = (const float*)d_in[3];
    const float* bq      = (const float*)d_in[4];
    const float* Wk      = (const float*)d_in[5];
    const float* bk      = (const float*)d_in[6];
    const float* Wv      = (const float*)d_in[7];
    const float* bv      = (const float*)d_in[8];
    float* out = (float*)d_out;

    __half *ITh, *ISh, *Wqh, *Wkh, *Wvh, *Qh, *Kh, *Vth, *Sh, *Fh, *Ah, *Ch;
    cudaGetSymbolAddress((void**)&ITh, g_ITh);
    cudaGetSymbolAddress((void**)&ISh, g_ISh);
    cudaGetSymbolAddress((void**)&Wqh, g_Wqh);
    cudaGetSymbolAddress((void**)&Wkh, g_Wkh);
    cudaGetSymbolAddress((void**)&Wvh, g_Wvh);
    cudaGetSymbolAddress((void**)&Qh,  g_Qh);
    cudaGetSymbolAddress((void**)&Kh,  g_Kh);
    cudaGetSymbolAddress((void**)&Vth, g_Vth);
    cudaGetSymbolAddress((void**)&Sh,  g_S);
    cudaGetSymbolAddress((void**)&Fh,  g_F);
    cudaGetSymbolAddress((void**)&Ah,  g_Ah);
    cudaGetSymbolAddress((void**)&Ch,  g_Ch);

    cudaFuncSetAttribute(hgemm<MODE_QK>,  cudaFuncAttributeMaxDynamicSharedMemorySize, SMEM_TOTAL);
    cudaFuncSetAttribute(hgemm<MODE_VT>,  cudaFuncAttributeMaxDynamicSharedMemorySize, SMEM_TOTAL);
    cudaFuncSetAttribute(hgemm<MODE_SC>,  cudaFuncAttributeMaxDynamicSharedMemorySize, SMEM_TOTAL);
    cudaFuncSetAttribute(hgemm<MODE_PV>,  cudaFuncAttributeMaxDynamicSharedMemorySize, SMEM_TOTAL);
    cudaFuncSetAttribute(hgemm<MODE_FIN>, cudaFuncAttributeMaxDynamicSharedMemorySize, SMEM_TOTAL);

    const float scale = 0.044194173824159216f;  // 1/sqrt(512)
    const long long sQKV = (long long)SEQ * DD;
    const long long sBUF = (long long)MTOT * DD;   // per-block Q/K/Vt/F stride
    const long long sS   = (long long)SEQ * SEQ;
    const long long sWW  = (long long)DD * DD;

    // input converts (5 launches)
    tohalf_kernel<<<2048, 256>>>(Itime,  ITh, MTOT * DD / 4);
    tohalf_kernel<<<2048, 256>>>(Ispace, ISh, MTOT * DD / 4);
    tohalf_kernel<<<512,  256>>>(Wq, Wqh, 4 * DD * DD / 4);
    tohalf_kernel<<<512,  256>>>(Wk, Wkh, 4 * DD * DD / 4);
    tohalf_kernel<<<512,  256>>>(Wv, Wvh, 4 * DD * DD / 4);

    // Input selection masks per weight-block z (bit z set -> use Ispace)
    // weights: 0=temporal_self(FTT), 1=spatial_self(FSS), 2=FTS, 3=FST
    // Q source:  z0 IT, z1 IS, z2 IT, z3 IS -> 0b1010
    // KV source: z0 IT, z1 IS, z2 IS, z3 IT -> 0b0110
    const uint32_t QMASK = 0xAu, KVMASK = 0x6u;

    // Projections, all 4 blocks batched in z (3 launches)
    dim3 gproj(DD / TN, MTOT / TM, 4);
    hgemm<MODE_QK><<<gproj, NTH, SMEM_TOTAL>>>(
        ITh, ISh, QMASK, Wqh, Qh, bq,
        DD, DD, DD, DD,
        0, 0, 0, sWW, 0, sBUF, DD, 1.0f);
    hgemm<MODE_QK><<<gproj, NTH, SMEM_TOTAL>>>(
        ITh, ISh, KVMASK, Wkh, Kh, bk,
        DD, DD, DD, DD,
        0, 0, 0, sWW, 0, sBUF, DD, 1.0f);
    hgemm<MODE_VT><<<gproj, NTH, SMEM_TOTAL>>>(
        ITh, ISh, KVMASK, Wvh, Vth, bv,
        DD, DD, MTOT, DD,
        0, 0, 0, sWW, 0, sBUF, DD, 1.0f);

    // Scores for all 4 blocks x 8 batches (z = blk*8 + batch)
    dim3 gsc(SEQ / TN, SEQ / TM, 32);
    hgemm<MODE_SC><<<gsc, NTH, SMEM_TOTAL>>>(
        Qh, Qh, 0, Kh, Sh, nullptr,
        DD, DD, SEQ, DD,
        8 * sQKV, sQKV, 8 * sQKV, sQKV, 8 * sS, sS, 0, scale);

    // Softmax all rows, in place
    softmax_kernel<<<32 * SEQ, 256>>>(Sh);

    // PV for all blocks/batches: F[z] = P[z] @ Vt[blk,:,batch-slice]^T
    dim3 gpv(DD / TN, SEQ / TM, 32);
    hgemm<MODE_PV><<<gpv, NTH, SMEM_TOTAL>>>(
        Sh, Sh, 0, Vth, Fh, nullptr,
        SEQ, MTOT, DD, SEQ,
        8 * sS, sS, sBUF, SEQ, 8 * sQKV, sQKV, 0, 1.0f);

    // Ah = FTT + FTS, Ch = FSS + FST
    fuse_kernel<<<1024, 256>>>(Fh, Ah, Ch, MTOT * DD / 8);

    // out[z] = A[z] @ C[z]^T + x_origin[z]
    dim3 gfin(SEQ / TN, SEQ / TM, BATCH);
    hgemm<MODE_FIN><<<gfin, NTH, SMEM_TOTAL>>>(
        Ah, Ah, 0, Ch, out, xorigin,
        DD, DD, SEQ, DD,
        0, sQKV, 0, sQKV, 0, sS, sS, 1.0f);
}

// round 7
// speedup vs baseline: 1.2802x; 1.0508x over previous
#include <cuda_runtime.h>
#include <cuda_fp16.h>
#include <stdint.h>
#include <math.h>

#define DD 512
#define BATCH 8
#define SEQ 2048
#define MTOT (BATCH * SEQ)   // 16384

#define TM 128
#define TN 128
#define BKK 64
#define NTH 256

#define STG_BYTES 32768           // A tile 16KB + B tile 16KB
#define NSTG 3
#define SMEM_TOTAL (NSTG * STG_BYTES)   // 98304; 2 CTAs/SM = 192KB

// ---------------- scratch (device globals; no allocation) ----------------
__device__ __align__(1024) __half g_ITh[MTOT * DD];                       // 16MB
__device__ __align__(1024) __half g_ISh[MTOT * DD];                       // 16MB
__device__ __align__(1024) __half g_Wqh[4 * DD * DD];
__device__ __align__(1024) __half g_Wkh[4 * DD * DD];
__device__ __align__(1024) __half g_Wvh[4 * DD * DD];
__device__ __align__(1024) __half g_Qh[4 * MTOT * DD];                    // 64MB  [blk][batch][tok][feat]
__device__ __align__(1024) __half g_Kh[4 * MTOT * DD];                    // 64MB
__device__ __align__(1024) __half g_Vth[4 * DD * MTOT];                   // 64MB  [blk][feat][tok]
__device__ __align__(1024) __half g_S[(size_t)32 * SEQ * SEQ];            // 256MB [blk*8+batch][q][k]
__device__ __align__(1024) __half g_F[(size_t)4 * MTOT * DD];             // 64MB  [blk][batch][tok][feat]
__device__ __align__(1024) __half g_Ah[MTOT * DD];                        // 16MB
__device__ __align__(1024) __half g_Ch[MTOT * DD];                        // 16MB

// ---------------- helpers ----------------
__device__ __forceinline__ uint32_t s2u(const void* p) {
    uint32_t a;
    asm("{ .reg .u64 t; cvta.to.shared.u64 t, %1; cvt.u32.u64 %0, t; }" : "=r"(a) : "l"(p));
    return a;
}
__device__ __forceinline__ void cp16(uint32_t dst, const void* src) {
    asm volatile("cp.async.cg.shared.global [%0], [%1], 16;" :: "r"(dst), "l"(src));
}
__device__ __forceinline__ void cp_commit() { asm volatile("cp.async.commit_group;" ::: "memory"); }
template <int N> __device__ __forceinline__ void cp_wait() {
    asm volatile("cp.async.wait_group %0;" :: "n"(N) : "memory");
}
__device__ __forceinline__ void ldsm4(uint32_t* d, uint32_t addr) {
    asm volatile("ldmatrix.sync.aligned.m8n8.x4.shared.b16 {%0,%1,%2,%3}, [%4];"
                 : "=r"(d[0]), "=r"(d[1]), "=r"(d[2]), "=r"(d[3]) : "r"(addr));
}
__device__ __forceinline__ void mma16816(float* c, const uint32_t* a, uint32_t b0, uint32_t b1) {
    asm volatile(
        "mma.sync.aligned.m16n8k16.row.col.f32.f16.f16.f32 "
        "{%0,%1,%2,%3},{%4,%5,%6,%7},{%8,%9},{%0,%1,%2,%3};"
        : "+f"(c[0]), "+f"(c[1]), "+f"(c[2]), "+f"(c[3])
        : "r"(a[0]), "r"(a[1]), "r"(a[2]), "r"(a[3]), "r"(b0), "r"(b1));
}

// ---------------------------------------------------------------------------
// NT GEMM: D[m,n] = sum_k A[m,k] * B[n,k]  (fp16 in, fp32 acc)
// CTA 128x128, 8 warps (2m x 4n), warp tile 64x32, 3-stage cp.async,
// one __syncthreads per K-chunk.
// z-batched: zh = z>>3, zl = z&7; operand offsets via hi/lo strides.
// A operand selected from {A0, A1} by bit z of amask.
// ---------------------------------------------------------------------------
enum { MODE_QK = 0, MODE_VT = 1, MODE_SC = 2, MODE_PV = 3, MODE_FIN = 4 };

template <int MODE>
__global__ __launch_bounds__(NTH, 2)
void hgemm(const __half* __restrict__ A0, const __half* __restrict__ A1, uint32_t amask,
           const __half* __restrict__ B, void* __restrict__ out, const float* __restrict__ X,
           int ldA, int ldB, int ldC, int K,
           long long sAhi, long long sAlo, long long sBhi, long long sBlo,
           long long sChi, long long sClo, long long sXlo,
           float alpha)
{
    extern __shared__ __align__(16) char smem[];
    const uint32_t sbase = s2u(smem);
    const int tid  = threadIdx.x;
    const int lane = tid & 31;
    const int warp = tid >> 5;
    const int wm = warp & 1;
    const int wn = warp >> 1;
    const int z  = blockIdx.z;
    const int zh = z >> 3, zl = z & 7;
    const int m0 = blockIdx.y * TM;
    const int n0 = blockIdx.x * TN;

    const __half* Ap = (((amask >> z) & 1) ? A1 : A0) + zh * sAhi + zl * sAlo;
    const __half* Bp = B + zh * sBhi + zl * sBlo;
    const size_t  co = (size_t)(zh * sChi + zl * sClo);

    float acc[4][4][4];
    #pragma unroll
    for (int i = 0; i < 4; i++)
        #pragma unroll
        for (int j = 0; j < 4; j++)
            #pragma unroll
            for (int e = 0; e < 4; e++) acc[i][j][e] = 0.f;

    const int nK = K / BKK;

    auto load_stage = [&](int ck, int stg) {
        const int k0 = ck * BKK;
        const uint32_t sb = sbase + stg * STG_BYTES;
        #pragma unroll
        for (int t = 0; t < 4; t++) {               // A: 128 rows x 128B
            int id = tid + t * NTH;
            int r = id >> 3, c = id & 7;
            cp16(sb + r * 128 + (((c ^ (r & 7)) & 7) << 4),
                 Ap + (size_t)(m0 + r) * ldA + k0 + c * 8);
        }
        #pragma unroll
        for (int t = 0; t < 4; t++) {               // B: 128 rows x 128B
            int id = tid + t * NTH;
            int r = id >> 3, c = id & 7;
            cp16(sb + 16384 + r * 128 + (((c ^ (r & 7)) & 7) << 4),
                 Bp + (size_t)(n0 + r) * ldB + k0 + c * 8);
        }
        cp_commit();
    };

    load_stage(0, 0);
    if (nK > 1) load_stage(1, 1);

    for (int i = 0; i < nK; i++) {
        if (i + 1 < nK) cp_wait<1>(); else cp_wait<0>();
        __syncthreads();
        // safe: slot (i+2)%3 was last read by stage i-1's compute, finished
        // by all warps before the sync above.
        if (i + 2 < nK) load_stage(i + 2, (i + 2) % 3);

        const uint32_t sA = sbase + (i % 3) * STG_BYTES;
        const uint32_t sB = sA + 16384;

        #pragma unroll
        for (int s = 0; s < 4; s++) {
            uint32_t af[4][4];
            #pragma unroll
            for (int im = 0; im < 4; im++) {
                int row = wm * 64 + im * 16 + (lane & 15);
                int ch  = 2 * s + (lane >> 4);
                ldsm4(af[im], sA + row * 128 + (((ch ^ (row & 7)) & 7) << 4));
            }
            uint32_t bf[2][4];
            #pragma unroll
            for (int j2 = 0; j2 < 2; j2++) {
                int row = wn * 32 + j2 * 16 + ((lane >> 4) << 3) + (lane & 7);
                int ch  = 2 * s + ((lane >> 3) & 1);
                ldsm4(bf[j2], sB + row * 128 + (((ch ^ (row & 7)) & 7) << 4));
            }
            #pragma unroll
            for (int im = 0; im < 4; im++)
                #pragma unroll
                for (int jn = 0; jn < 4; jn++)
                    mma16816(acc[im][jn], af[im], bf[jn >> 1][(jn & 1) * 2],
                             bf[jn >> 1][(jn & 1) * 2 + 1]);
        }
        __syncthreads();
    }

    // ---------------- epilogue ----------------
    const int lm = lane >> 2;
    const int ln = (lane & 3) * 2;

    if (MODE == MODE_VT) {
        // transpose via smem: st[n_local][m_local], stride 136 halves
        __half* st = (__half*)smem;
        const float* Xp = X + zl * sXlo;
        #pragma unroll
        for (int im = 0; im < 4; im++) {
            int ml = wm * 64 + im * 16 + lm;
            #pragma unroll
            for (int jn = 0; jn < 4; jn++) {
                int nl = wn * 32 + jn * 8 + ln;
                float b0 = Xp[n0 + nl], b1 = Xp[n0 + nl + 1];
                st[nl * 136 + ml]           = __float2half(acc[im][jn][0] + b0);
                st[(nl + 1) * 136 + ml]     = __float2half(acc[im][jn][1] + b1);
                st[nl * 136 + ml + 8]       = __float2half(acc[im][jn][2] + b0);
                st[(nl + 1) * 136 + ml + 8] = __float2half(acc[im][jn][3] + b1);
            }
        }
        __syncthreads();
        __half* O = (__half*)out + co;
        #pragma unroll
        for (int t = 0; t < 8; t++) {
            int idx = tid + t * NTH;             // 2048 chunks of 16B
            int r = idx >> 4, sgl = idx & 15;
            uint4 v = *(const uint4*)(st + r * 136 + sgl * 8);
            *(uint4*)(O + (size_t)(n0 + r) * ldC + m0 + sgl * 8) = v;
        }
        return;
    }

    #pragma unroll
    for (int im = 0; im < 4; im++) {
        int r0 = m0 + wm * 64 + im * 16 + lm;
        int r1 = r0 + 8;
        #pragma unroll
        for (int jn = 0; jn < 4; jn++) {
            int c = n0 + wn * 32 + jn * 8 + ln;
            float v0 = acc[im][jn][0], v1 = acc[im][jn][1];
            float v2 = acc[im][jn][2], v3 = acc[im][jn][3];
            if (MODE == MODE_QK) {
                __half* O = (__half*)out + co;
                const float* Xp = X + zl * sXlo;
                float b0 = Xp[c], b1 = Xp[c + 1];
                *(__half2*)(O + (size_t)r0 * ldC + c) = __floats2half2_rn(v0 + b0, v1 + b1);
                *(__half2*)(O + (size_t)r1 * ldC + c) = __floats2half2_rn(v2 + b0, v3 + b1);
            } else if (MODE == MODE_SC) {
                __half* O = (__half*)out + co;
                *(__half2*)(O + (size_t)r0 * ldC + c) = __floats2half2_rn(v0 * alpha, v1 * alpha);
                *(__half2*)(O + (size_t)r1 * ldC + c) = __floats2half2_rn(v2 * alpha, v3 * alpha);
            } else if (MODE == MODE_PV) {
                __half* O = (__half*)out + co;
                *(__half2*)(O + (size_t)r0 * ldC + c) = __floats2half2_rn(v0, v1);
                *(__half2*)(O + (size_t)r1 * ldC + c) = __floats2half2_rn(v2, v3);
            } else {  // MODE_FIN
                float* O = (float*)out + co;
                const float* Xz = X + zl * sXlo;
                size_t o0 = (size_t)r0 * ldC + c, o1 = (size_t)r1 * ldC + c;
                float2 p0 = *(const float2*)(Xz + o0), p1 = *(const float2*)(Xz + o1);
                *(float2*)(O + o0) = make_float2(v0 + p0.x, v1 + p0.y);
                *(float2*)(O + o1) = make_float2(v2 + p1.x, v3 + p1.y);
            }
        }
    }
}

// ---------------------------------------------------------------------------
// Fused fp32 -> fp16 convert of all 5 inputs in one launch
// ---------------------------------------------------------------------------
#define N4_IN (MTOT * DD / 4)        // 2097152
#define N4_W  (4 * DD * DD / 4)      // 262144
__global__ __launch_bounds__(256)
void convert_all(const float* __restrict__ IT, const float* __restrict__ IS,
                 const float* __restrict__ Wq, const float* __restrict__ Wk,
                 const float* __restrict__ Wv,
                 __half* __restrict__ oIT, __half* __restrict__ oIS,
                 __half* __restrict__ oWq, __half* __restrict__ oWk,
                 __half* __restrict__ oWv)
{
    const int total = 2 * N4_IN + 3 * N4_W;
    int idx = blockIdx.x * blockDim.x + threadIdx.x;
    int stride = gridDim.x * blockDim.x;
    for (int i = idx; i < total; i += stride) {
        const float4* s; __half2* d; int off;
        if (i < N4_IN)                     { s = (const float4*)IT; d = (__half2*)oIT; off = i; }
        else if (i < 2 * N4_IN)            { s = (const float4*)IS; d = (__half2*)oIS; off = i - N4_IN; }
        else if (i < 2 * N4_IN + N4_W)     { s = (const float4*)Wq; d = (__half2*)oWq; off = i - 2 * N4_IN; }
        else if (i < 2 * N4_IN + 2 * N4_W) { s = (const float4*)Wk; d = (__half2*)oWk; off = i - 2 * N4_IN - N4_W; }
        else                               { s = (const float4*)Wv; d = (__half2*)oWv; off = i - 2 * N4_IN - 2 * N4_W; }
        float4 v = s[off];
        d[off * 2]     = __floats2half2_rn(v.x, v.y);
        d[off * 2 + 1] = __floats2half2_rn(v.z, v.w);
    }
}

// ---------------------------------------------------------------------------
// Ah = F[0] + F[2]  (FTT + FTS),   Ch = F[1] + F[3]  (FSS + FST)
// ---------------------------------------------------------------------------
__global__ __launch_bounds__(256)
void fuse_kernel(const __half* __restrict__ F, __half* __restrict__ Ah,
                 __half* __restrict__ Ch, int n8)
{
    const size_t blk = (size_t)MTOT * DD;
    int idx = blockIdx.x * blockDim.x + threadIdx.x;
    int stride = gridDim.x * blockDim.x;
    const uint4* fTT = (const uint4*)F;
    const uint4* fSS = (const uint4*)(F + blk);
    const uint4* fTS = (const uint4*)(F + 2 * blk);
    const uint4* fST = (const uint4*)(F + 3 * blk);
    uint4* a4 = (uint4*)Ah;
    uint4* c4 = (uint4*)Ch;
    for (int i = idx; i < n8; i += stride) {
        uint4 x = fTT[i], y = fTS[i], r;
        ((__half2*)&r)[0] = __hadd2(((__half2*)&x)[0], ((__half2*)&y)[0]);
        ((__half2*)&r)[1] = __hadd2(((__half2*)&x)[1], ((__half2*)&y)[1]);
        ((__half2*)&r)[2] = __hadd2(((__half2*)&x)[2], ((__half2*)&y)[2]);
        ((__half2*)&r)[3] = __hadd2(((__half2*)&x)[3], ((__half2*)&y)[3]);
        a4[i] = r;
        x = fSS[i]; y = fST[i];
        ((__half2*)&r)[0] = __hadd2(((__half2*)&x)[0], ((__half2*)&y)[0]);
        ((__half2*)&r)[1] = __hadd2(((__half2*)&x)[1], ((__half2*)&y)[1]);
        ((__half2*)&r)[2] = __hadd2(((__half2*)&x)[2], ((__half2*)&y)[2]);
        ((__half2*)&r)[3] = __hadd2(((__half2*)&x)[3], ((__half2*)&y)[3]);
        c4[i] = r;
    }
}

// ---------------------------------------------------------------------------
// Row softmax over 2048 fp16 cols, in place; shuffle reductions, 2 syncs.
// ---------------------------------------------------------------------------
__global__ __launch_bounds__(256)
void softmax_kernel(__half* __restrict__ S)
{
    const size_t base = (size_t)blockIdx.x * SEQ;
    const int tid  = threadIdx.x;
    const int lane = tid & 31;
    const int warp = tid >> 5;

    uint4 v = ((const uint4*)(S + base))[tid];
    __half2* h = (__half2*)&v;
    float vals[8];
    #pragma unroll
    for (int i = 0; i < 4; i++) {
        float2 f = __half22float2(h[i]);
        vals[2 * i] = f.x; vals[2 * i + 1] = f.y;
    }

    float m = vals[0];
    #pragma unroll
    for (int i = 1; i < 8; i++) m = fmaxf(m, vals[i]);
    #pragma unroll
    for (int s = 16; s > 0; s >>= 1) m = fmaxf(m, __shfl_xor_sync(0xffffffffu, m, s));

    __shared__ float redm[8], reds[8];
    if (lane == 0) redm[warp] = m;
    __syncthreads();
    #pragma unroll
    for (int w = 0; w < 8; w++) m = fmaxf(m, redm[w]);

    float sum = 0.f;
    #pragma unroll
    for (int i = 0; i < 8; i++) { vals[i] = __expf(vals[i] - m); sum += vals[i]; }
    #pragma unroll
    for (int s = 16; s > 0; s >>= 1) sum += __shfl_xor_sync(0xffffffffu, sum, s);
    if (lane == 0) reds[warp] = sum;
    __syncthreads();
    sum = 0.f;
    #pragma unroll
    for (int w = 0; w < 8; w++) sum += reds[w];
    float inv = 1.0f / sum;

    #pragma unroll
    for (int i = 0; i < 4; i++)
        h[i] = __floats2half2_rn(vals[2 * i] * inv, vals[2 * i + 1] * inv);
    ((uint4*)(S + base))[tid] = v;
}

// ---------------------------------------------------------------------------
extern "C" void kernel_launch(void* const* d_in, const int* in_sizes, int n_in,
                              void* d_out, int out_size)
{
    const float* Itime   = (const float*)d_in[0];
    const float* Ispace  = (const float*)d_in[1];
    const float* xorigin = (const float*)d_in[2];
    const float* Wq      = (const float*)d_in[3];
    const float* bq      = (const float*)d_in[4];
    const float* Wk      = (const float*)d_in[5];
    const float* bk      = (const float*)d_in[6];
    const float* Wv      = (const float*)d_in[7];
    const float* bv      = (const float*)d_in[8];
    float* out = (float*)d_out;

    __half *ITh, *ISh, *Wqh, *Wkh, *Wvh, *Qh, *Kh, *Vth, *Sh, *Fh, *Ah, *Ch;
    cudaGetSymbolAddress((void**)&ITh, g_ITh);
    cudaGetSymbolAddress((void**)&ISh, g_ISh);
    cudaGetSymbolAddress((void**)&Wqh, g_Wqh);
    cudaGetSymbolAddress((void**)&Wkh, g_Wkh);
    cudaGetSymbolAddress((void**)&Wvh, g_Wvh);
    cudaGetSymbolAddress((void**)&Qh,  g_Qh);
    cudaGetSymbolAddress((void**)&Kh,  g_Kh);
    cudaGetSymbolAddress((void**)&Vth, g_Vth);
    cudaGetSymbolAddress((void**)&Sh,  g_S);
    cudaGetSymbolAddress((void**)&Fh,  g_F);
    cudaGetSymbolAddress((void**)&Ah,  g_Ah);
    cudaGetSymbolAddress((void**)&Ch,  g_Ch);

    cudaFuncSetAttribute(hgemm<MODE_QK>,  cudaFuncAttributeMaxDynamicSharedMemorySize, SMEM_TOTAL);
    cudaFuncSetAttribute(hgemm<MODE_VT>,  cudaFuncAttributeMaxDynamicSharedMemorySize, SMEM_TOTAL);
    cudaFuncSetAttribute(hgemm<MODE_SC>,  cudaFuncAttributeMaxDynamicSharedMemorySize, SMEM_TOTAL);
    cudaFuncSetAttribute(hgemm<MODE_PV>,  cudaFuncAttributeMaxDynamicSharedMemorySize, SMEM_TOTAL);
    cudaFuncSetAttribute(hgemm<MODE_FIN>, cudaFuncAttributeMaxDynamicSharedMemorySize, SMEM_TOTAL);

    const float scale = 0.044194173824159216f;  // 1/sqrt(512)
    const long long sQKV = (long long)SEQ * DD;
    const long long sBUF = (long long)MTOT * DD;   // per-block Q/K/Vt/F stride
    const long long sS   = (long long)SEQ * SEQ;
    const long long sWW  = (long long)DD * DD;

    // all input converts in one launch
    convert_all<<<4096, 256>>>(Itime, Ispace, Wq, Wk, Wv, ITh, ISh, Wqh, Wkh, Wvh);

    // Input selection masks per weight-block z (bit z set -> use Ispace)
    // weights: 0=temporal_self(FTT), 1=spatial_self(FSS), 2=FTS, 3=FST
    const uint32_t QMASK = 0xAu, KVMASK = 0x6u;

    // Projections, all 4 blocks batched in z (3 launches)
    dim3 gproj(DD / TN, MTOT / TM, 4);
    hgemm<MODE_QK><<<gproj, NTH, SMEM_TOTAL>>>(
        ITh, ISh, QMASK, Wqh, Qh, bq,
        DD, DD, DD, DD,
        0, 0, 0, sWW, 0, sBUF, DD, 1.0f);
    hgemm<MODE_QK><<<gproj, NTH, SMEM_TOTAL>>>(
        ITh, ISh, KVMASK, Wkh, Kh, bk,
        DD, DD, DD, DD,
        0, 0, 0, sWW, 0, sBUF, DD, 1.0f);
    hgemm<MODE_VT><<<gproj, NTH, SMEM_TOTAL>>>(
        ITh, ISh, KVMASK, Wvh, Vth, bv,
        DD, DD, MTOT, DD,
        0, 0, 0, sWW, 0, sBUF, DD, 1.0f);

    // Scores for all 4 blocks x 8 batches (z = blk*8 + batch)
    dim3 gsc(SEQ / TN, SEQ / TM, 32);
    hgemm<MODE_SC><<<gsc, NTH, SMEM_TOTAL>>>(
        Qh, Qh, 0, Kh, Sh, nullptr,
        DD, DD, SEQ, DD,
        8 * sQKV, sQKV, 8 * sQKV, sQKV, 8 * sS, sS, 0, scale);

    // Softmax all rows, in place
    softmax_kernel<<<32 * SEQ, 256>>>(Sh);

    // PV for all blocks/batches: F[z] = P[z] @ Vt[blk,:,batch-slice]^T
    dim3 gpv(DD / TN, SEQ / TM, 32);
    hgemm<MODE_PV><<<gpv, NTH, SMEM_TOTAL>>>(
        Sh, Sh, 0, Vth, Fh, nullptr,
        SEQ, MTOT, DD, SEQ,
        8 * sS, sS, sBUF, SEQ, 8 * sQKV, sQKV, 0, 1.0f);

    // Ah = FTT + FTS, Ch = FSS + FST
    fuse_kernel<<<1024, 256>>>(Fh, Ah, Ch, MTOT * DD / 8);

    // out[z] = A[z] @ C[z]^T + x_origin[z]
    dim3 gfin(SEQ / TN, SEQ / TM, BATCH);
    hgemm<MODE_FIN><<<gfin, NTH, SMEM_TOTAL>>>(
        Ah, Ah, 0, Ch, out, xorigin,
        DD, DD, SEQ, DD,
        0, sQKV, 0, sQKV, 0, sS, sS, 1.0f);
}

// round 8
// speedup vs baseline: 1.3141x; 1.0265x over previous
#include <cuda_runtime.h>
#include <cuda_fp16.h>
#include <stdint.h>
#include <math.h>

#define DD 512
#define BATCH 8
#define SEQ 2048
#define MTOT (BATCH * SEQ)   // 16384

#define TM 128
#define TN 128
#define BKK 64
#define NTH 128              // 4 warps: 2m x 2n, warp tile 64x64

#define STG_BYTES 32768           // A tile 16KB + B tile 16KB
#define NSTG 3
#define SMEM_TOTAL (NSTG * STG_BYTES)   // 98304; 2 CTAs/SM = 192KB

// ---------------- scratch (device globals; no allocation) ----------------
__device__ __align__(1024) __half g_ITh[MTOT * DD];                       // 16MB
__device__ __align__(1024) __half g_ISh[MTOT * DD];                       // 16MB
__device__ __align__(1024) __half g_Wqh[4 * DD * DD];
__device__ __align__(1024) __half g_Wkh[4 * DD * DD];
__device__ __align__(1024) __half g_Wvh[4 * DD * DD];
__device__ __align__(1024) __half g_Qh[4 * MTOT * DD];                    // 64MB
__device__ __align__(1024) __half g_Kh[4 * MTOT * DD];                    // 64MB
__device__ __align__(1024) __half g_Vth[4 * DD * MTOT];                   // 64MB [blk][feat][tok]
__device__ __align__(1024) __half g_S[(size_t)32 * SEQ * SEQ];            // 256MB
__device__ __align__(1024) __half g_F[(size_t)4 * MTOT * DD];             // 64MB
__device__ __align__(1024) __half g_Ah[MTOT * DD];                        // 16MB
__device__ __align__(1024) __half g_Ch[MTOT * DD];                        // 16MB

// ---------------- helpers ----------------
__device__ __forceinline__ uint32_t s2u(const void* p) {
    uint32_t a;
    asm("{ .reg .u64 t; cvta.to.shared.u64 t, %1; cvt.u32.u64 %0, t; }" : "=r"(a) : "l"(p));
    return a;
}
__device__ __forceinline__ void cp16(uint32_t dst, const void* src) {
    asm volatile("cp.async.cg.shared.global [%0], [%1], 16;" :: "r"(dst), "l"(src));
}
__device__ __forceinline__ void cp_commit() { asm volatile("cp.async.commit_group;" ::: "memory"); }
template <int N> __device__ __forceinline__ void cp_wait() {
    asm volatile("cp.async.wait_group %0;" :: "n"(N) : "memory");
}
__device__ __forceinline__ void ldsm4(uint32_t* d, uint32_t addr) {
    asm volatile("ldmatrix.sync.aligned.m8n8.x4.shared.b16 {%0,%1,%2,%3}, [%4];"
                 : "=r"(d[0]), "=r"(d[1]), "=r"(d[2]), "=r"(d[3]) : "r"(addr));
}
__device__ __forceinline__ void mma16816(float* c, const uint32_t* a, uint32_t b0, uint32_t b1) {
    asm volatile(
        "mma.sync.aligned.m16n8k16.row.col.f32.f16.f16.f32 "
        "{%0,%1,%2,%3},{%4,%5,%6,%7},{%8,%9},{%0,%1,%2,%3};"
        : "+f"(c[0]), "+f"(c[1]), "+f"(c[2]), "+f"(c[3])
        : "r"(a[0]), "r"(a[1]), "r"(a[2]), "r"(a[3]), "r"(b0), "r"(b1));
}

// ---------------------------------------------------------------------------
// NT GEMM: D[m,n] = sum_k A[m,k] * B[n,k]  (fp16 in, fp32 acc)
// CTA 128x128, 4 warps (2m x 2n), warp tile 64x64, 3-stage cp.async.
// 2 CTAs/SM -> two independent barrier groups hide sync/load latency.
// ---------------------------------------------------------------------------
enum { MODE_QK = 0, MODE_VT = 1, MODE_SC = 2, MODE_PV = 3, MODE_FIN = 4 };

template <int MODE>
__global__ __launch_bounds__(NTH, 2)
void hgemm(const __half* __restrict__ A0, const __half* __restrict__ A1, uint32_t amask,
           const __half* __restrict__ B, void* __restrict__ out, const float* __restrict__ X,
           int ldA, int ldB, int ldC, int K,
           long long sAhi, long long sAlo, long long sBhi, long long sBlo,
           long long sChi, long long sClo, long long sXlo,
           float alpha)
{
    extern __shared__ __align__(16) char smem[];
    const uint32_t sbase = s2u(smem);
    const int tid  = threadIdx.x;
    const int lane = tid & 31;
    const int warp = tid >> 5;          // 0..3
    const int wm = warp & 1;            // m half (64)
    const int wn = warp >> 1;           // n half (64)
    const int z  = blockIdx.z;
    const int zh = z >> 3, zl = z & 7;
    const int m0 = blockIdx.y * TM;
    const int n0 = blockIdx.x * TN;

    const __half* Ap = (((amask >> z) & 1) ? A1 : A0) + zh * sAhi + zl * sAlo;
    const __half* Bp = B + zh * sBhi + zl * sBlo;
    const size_t  co = (size_t)(zh * sChi + zl * sClo);

    float acc[4][8][4];
    #pragma unroll
    for (int i = 0; i < 4; i++)
        #pragma unroll
        for (int j = 0; j < 8; j++)
            #pragma unroll
            for (int e = 0; e < 4; e++) acc[i][j][e] = 0.f;

    const int nK = K / BKK;

    auto load_stage = [&](int ck, int stg) {
        const int k0 = ck * BKK;
        const uint32_t sb = sbase + stg * STG_BYTES;
        #pragma unroll
        for (int t = 0; t < 8; t++) {               // A: 128 rows x 128B
            int id = tid + t * NTH;
            int r = id >> 3, c = id & 7;
            cp16(sb + r * 128 + (((c ^ (r & 7)) & 7) << 4),
                 Ap + (size_t)(m0 + r) * ldA + k0 + c * 8);
        }
        #pragma unroll
        for (int t = 0; t < 8; t++) {               // B: 128 rows x 128B
            int id = tid + t * NTH;
            int r = id >> 3, c = id & 7;
            cp16(sb + 16384 + r * 128 + (((c ^ (r & 7)) & 7) << 4),
                 Bp + (size_t)(n0 + r) * ldB + k0 + c * 8);
        }
        cp_commit();
    };

    load_stage(0, 0);
    if (nK > 1) load_stage(1, 1);

    for (int i = 0; i < nK; i++) {
        if (i + 1 < nK) cp_wait<1>(); else cp_wait<0>();
        __syncthreads();
        if (i + 2 < nK) load_stage(i + 2, (i + 2) % 3);

        const uint32_t sA = sbase + (i % 3) * STG_BYTES;
        const uint32_t sB = sA + 16384;

        #pragma unroll
        for (int s = 0; s < 4; s++) {
            uint32_t af[4][4];
            #pragma unroll
            for (int im = 0; im < 4; im++) {
                int row = wm * 64 + im * 16 + (lane & 15);
                int ch  = 2 * s + (lane >> 4);
                ldsm4(af[im], sA + row * 128 + (((ch ^ (row & 7)) & 7) << 4));
            }
            uint32_t bf[4][4];
            #pragma unroll
            for (int j2 = 0; j2 < 4; j2++) {
                int row = wn * 64 + j2 * 16 + ((lane >> 4) << 3) + (lane & 7);
                int ch  = 2 * s + ((lane >> 3) & 1);
                ldsm4(bf[j2], sB + row * 128 + (((ch ^ (row & 7)) & 7) << 4));
            }
            #pragma unroll
            for (int im = 0; im < 4; im++)
                #pragma unroll
                for (int jn = 0; jn < 8; jn++)
                    mma16816(acc[im][jn], af[im], bf[jn >> 1][(jn & 1) * 2],
                             bf[jn >> 1][(jn & 1) * 2 + 1]);
        }
        __syncthreads();
    }

    // ---------------- epilogue ----------------
    const int lm = lane >> 2;
    const int ln = (lane & 3) * 2;

    if (MODE == MODE_VT) {
        // transpose via smem: st[n_local][m_local], stride 136 halves
        __half* st = (__half*)smem;
        const float* Xp = X + zl * sXlo;
        #pragma unroll
        for (int im = 0; im < 4; im++) {
            int ml = wm * 64 + im * 16 + lm;
            #pragma unroll
            for (int jn = 0; jn < 8; jn++) {
                int nl = wn * 64 + jn * 8 + ln;
                float b0 = Xp[n0 + nl], b1 = Xp[n0 + nl + 1];
                st[nl * 136 + ml]           = __float2half(acc[im][jn][0] + b0);
                st[(nl + 1) * 136 + ml]     = __float2half(acc[im][jn][1] + b1);
                st[nl * 136 + ml + 8]       = __float2half(acc[im][jn][2] + b0);
                st[(nl + 1) * 136 + ml + 8] = __float2half(acc[im][jn][3] + b1);
            }
        }
        __syncthreads();
        __half* O = (__half*)out + co;
        #pragma unroll
        for (int t = 0; t < 16; t++) {
            int idx = tid + t * NTH;             // 2048 chunks of 16B
            int r = idx >> 4, sgl = idx & 15;
            uint4 v = *(const uint4*)(st + r * 136 + sgl * 8);
            *(uint4*)(O + (size_t)(n0 + r) * ldC + m0 + sgl * 8) = v;
        }
        return;
    }

    #pragma unroll
    for (int im = 0; im < 4; im++) {
        int r0 = m0 + wm * 64 + im * 16 + lm;
        int r1 = r0 + 8;
        #pragma unroll
        for (int jn = 0; jn < 8; jn++) {
            int c = n0 + wn * 64 + jn * 8 + ln;
            float v0 = acc[im][jn][0], v1 = acc[im][jn][1];
            float v2 = acc[im][jn][2], v3 = acc[im][jn][3];
            if (MODE == MODE_QK) {
                __half* O = (__half*)out + co;
                const float* Xp = X + zl * sXlo;
                float b0 = Xp[c], b1 = Xp[c + 1];
                *(__half2*)(O + (size_t)r0 * ldC + c) = __floats2half2_rn(v0 + b0, v1 + b1);
                *(__half2*)(O + (size_t)r1 * ldC + c) = __floats2half2_rn(v2 + b0, v3 + b1);
            } else if (MODE == MODE_SC) {
                __half* O = (__half*)out + co;
                *(__half2*)(O + (size_t)r0 * ldC + c) = __floats2half2_rn(v0 * alpha, v1 * alpha);
                *(__half2*)(O + (size_t)r1 * ldC + c) = __floats2half2_rn(v2 * alpha, v3 * alpha);
            } else if (MODE == MODE_PV) {
                __half* O = (__half*)out + co;
                *(__half2*)(O + (size_t)r0 * ldC + c) = __floats2half2_rn(v0, v1);
                *(__half2*)(O + (size_t)r1 * ldC + c) = __floats2half2_rn(v2, v3);
            } else {  // MODE_FIN
                float* O = (float*)out + co;
                const float* Xz = X + zl * sXlo;
                size_t o0 = (size_t)r0 * ldC + c, o1 = (size_t)r1 * ldC + c;
                float2 p0 = *(const float2*)(Xz + o0), p1 = *(const float2*)(Xz + o1);
                *(float2*)(O + o0) = make_float2(v0 + p0.x, v1 + p0.y);
                *(float2*)(O + o1) = make_float2(v2 + p1.x, v3 + p1.y);
            }
        }
    }
}

// ---------------------------------------------------------------------------
// Fused fp32 -> fp16 convert of all 5 inputs in one launch
// ---------------------------------------------------------------------------
#define N4_IN (MTOT * DD / 4)        // 2097152
#define N4_W  (4 * DD * DD / 4)      // 262144
__global__ __launch_bounds__(256)
void convert_all(const float* __restrict__ IT, const float* __restrict__ IS,
                 const float* __restrict__ Wq, const float* __restrict__ Wk,
                 const float* __restrict__ Wv,
                 __half* __restrict__ oIT, __half* __restrict__ oIS,
                 __half* __restrict__ oWq, __half* __restrict__ oWk,
                 __half* __restrict__ oWv)
{
    const int total = 2 * N4_IN + 3 * N4_W;
    int idx = blockIdx.x * blockDim.x + threadIdx.x;
    int stride = gridDim.x * blockDim.x;
    for (int i = idx; i < total; i += stride) {
        const float4* s; __half2* d; int off;
        if (i < N4_IN)                     { s = (const float4*)IT; d = (__half2*)oIT; off = i; }
        else if (i < 2 * N4_IN)            { s = (const float4*)IS; d = (__half2*)oIS; off = i - N4_IN; }
        else if (i < 2 * N4_IN + N4_W)     { s = (const float4*)Wq; d = (__half2*)oWq; off = i - 2 * N4_IN; }
        else if (i < 2 * N4_IN + 2 * N4_W) { s = (const float4*)Wk; d = (__half2*)oWk; off = i - 2 * N4_IN - N4_W; }
        else                               { s = (const float4*)Wv; d = (__half2*)oWv; off = i - 2 * N4_IN - 2 * N4_W; }
        float4 v = s[off];
        d[off * 2]     = __floats2half2_rn(v.x, v.y);
        d[off * 2 + 1] = __floats2half2_rn(v.z, v.w);
    }
}

// ---------------------------------------------------------------------------
// Ah = F[0] + F[2]  (FTT + FTS),   Ch = F[1] + F[3]  (FSS + FST)
// ---------------------------------------------------------------------------
__global__ __launch_bounds__(256)
void fuse_kernel(const __half* __restrict__ F, __half* __restrict__ Ah,
                 __half* __restrict__ Ch, int n8)
{
    const size_t blk = (size_t)MTOT * DD;
    int idx = blockIdx.x * blockDim.x + threadIdx.x;
    int stride = gridDim.x * blockDim.x;
    const uint4* fTT = (const uint4*)F;
    const uint4* fSS = (const uint4*)(F + blk);
    const uint4* fTS = (const uint4*)(F + 2 * blk);
    const uint4* fST = (const uint4*)(F + 3 * blk);
    uint4* a4 = (uint4*)Ah;
    uint4* c4 = (uint4*)Ch;
    for (int i = idx; i < n8; i += stride) {
        uint4 x = fTT[i], y = fTS[i], r;
        ((__half2*)&r)[0] = __hadd2(((__half2*)&x)[0], ((__half2*)&y)[0]);
        ((__half2*)&r)[1] = __hadd2(((__half2*)&x)[1], ((__half2*)&y)[1]);
        ((__half2*)&r)[2] = __hadd2(((__half2*)&x)[2], ((__half2*)&y)[2]);
        ((__half2*)&r)[3] = __hadd2(((__half2*)&x)[3], ((__half2*)&y)[3]);
        a4[i] = r;
        x = fSS[i]; y = fST[i];
        ((__half2*)&r)[0] = __hadd2(((__half2*)&x)[0], ((__half2*)&y)[0]);
        ((__half2*)&r)[1] = __hadd2(((__half2*)&x)[1], ((__half2*)&y)[1]);
        ((__half2*)&r)[2] = __hadd2(((__half2*)&x)[2], ((__half2*)&y)[2]);
        ((__half2*)&r)[3] = __hadd2(((__half2*)&x)[3], ((__half2*)&y)[3]);
        c4[i] = r;
    }
}

// ---------------------------------------------------------------------------
// Row softmax over 2048 fp16 cols, in place; shuffle reductions, 2 syncs.
// ---------------------------------------------------------------------------
__global__ __launch_bounds__(256)
void softmax_kernel(__half* __restrict__ S)
{
    const size_t base = (size_t)blockIdx.x * SEQ;
    const int tid  = threadIdx.x;
    const int lane = tid & 31;
    const int warp = tid >> 5;

    uint4 v = ((const uint4*)(S + base))[tid];
    __half2* h = (__half2*)&v;
    float vals[8];
    #pragma unroll
    for (int i = 0; i < 4; i++) {
        float2 f = __half22float2(h[i]);
        vals[2 * i] = f.x; vals[2 * i + 1] = f.y;
    }

    float m = vals[0];
    #pragma unroll
    for (int i = 1; i < 8; i++) m = fmaxf(m, vals[i]);
    #pragma unroll
    for (int s = 16; s > 0; s >>= 1) m = fmaxf(m, __shfl_xor_sync(0xffffffffu, m, s));

    __shared__ float redm[8], reds[8];
    if (lane == 0) redm[warp] = m;
    __syncthreads();
    #pragma unroll
    for (int w = 0; w < 8; w++) m = fmaxf(m, redm[w]);

    float sum = 0.f;
    #pragma unroll
    for (int i = 0; i < 8; i++) { vals[i] = __expf(vals[i] - m); sum += vals[i]; }
    #pragma unroll
    for (int s = 16; s > 0; s >>= 1) sum += __shfl_xor_sync(0xffffffffu, sum, s);
    if (lane == 0) reds[warp] = sum;
    __syncthreads();
    sum = 0.f;
    #pragma unroll
    for (int w = 0; w < 8; w++) sum += reds[w];
    float inv = 1.0f / sum;

    #pragma unroll
    for (int i = 0; i < 4; i++)
        h[i] = __floats2half2_rn(vals[2 * i] * inv, vals[2 * i + 1] * inv);
    ((uint4*)(S + base))[tid] = v;
}

// ---------------------------------------------------------------------------
extern "C" void kernel_launch(void* const* d_in, const int* in_sizes, int n_in,
                              void* d_out, int out_size)
{
    const float* Itime   = (const float*)d_in[0];
    const float* Ispace  = (const float*)d_in[1];
    const float* xorigin = (const float*)d_in[2];
    const float* Wq      = (const float*)d_in[3];
    const float* bq      = (const float*)d_in[4];
    const float* Wk      = (const float*)d_in[5];
    const float* bk      = (const float*)d_in[6];
    const float* Wv      = (const float*)d_in[7];
    const float* bv      = (const float*)d_in[8];
    float* out = (float*)d_out;

    __half *ITh, *ISh, *Wqh, *Wkh, *Wvh, *Qh, *Kh, *Vth, *Sh, *Fh, *Ah, *Ch;
    cudaGetSymbolAddress((void**)&ITh, g_ITh);
    cudaGetSymbolAddress((void**)&ISh, g_ISh);
    cudaGetSymbolAddress((void**)&Wqh, g_Wqh);
    cudaGetSymbolAddress((void**)&Wkh, g_Wkh);
    cudaGetSymbolAddress((void**)&Wvh, g_Wvh);
    cudaGetSymbolAddress((void**)&Qh,  g_Qh);
    cudaGetSymbolAddress((void**)&Kh,  g_Kh);
    cudaGetSymbolAddress((void**)&Vth, g_Vth);
    cudaGetSymbolAddress((void**)&Sh,  g_S);
    cudaGetSymbolAddress((void**)&Fh,  g_F);
    cudaGetSymbolAddress((void**)&Ah,  g_Ah);
    cudaGetSymbolAddress((void**)&Ch,  g_Ch);

    cudaFuncSetAttribute(hgemm<MODE_QK>,  cudaFuncAttributeMaxDynamicSharedMemorySize, SMEM_TOTAL);
    cudaFuncSetAttribute(hgemm<MODE_VT>,  cudaFuncAttributeMaxDynamicSharedMemorySize, SMEM_TOTAL);
    cudaFuncSetAttribute(hgemm<MODE_SC>,  cudaFuncAttributeMaxDynamicSharedMemorySize, SMEM_TOTAL);
    cudaFuncSetAttribute(hgemm<MODE_PV>,  cudaFuncAttributeMaxDynamicSharedMemorySize, SMEM_TOTAL);
    cudaFuncSetAttribute(hgemm<MODE_FIN>, cudaFuncAttributeMaxDynamicSharedMemorySize, SMEM_TOTAL);

    const float scale = 0.044194173824159216f;  // 1/sqrt(512)
    const long long sQKV = (long long)SEQ * DD;
    const long long sBUF = (long long)MTOT * DD;   // per-block Q/K/Vt/F stride
    const long long sS   = (long long)SEQ * SEQ;
    const long long sWW  = (long long)DD * DD;

    // all input converts in one launch
    convert_all<<<4096, 256>>>(Itime, Ispace, Wq, Wk, Wv, ITh, ISh, Wqh, Wkh, Wvh);

    // Input selection masks per weight-block z (bit z set -> use Ispace)
    const uint32_t QMASK = 0xAu, KVMASK = 0x6u;

    // Projections, all 4 blocks batched in z (3 launches)
    dim3 gproj(DD / TN, MTOT / TM, 4);
    hgemm<MODE_QK><<<gproj, NTH, SMEM_TOTAL>>>(
        ITh, ISh, QMASK, Wqh, Qh, bq,
        DD, DD, DD, DD,
        0, 0, 0, sWW, 0, sBUF, DD, 1.0f);
    hgemm<MODE_QK><<<gproj, NTH, SMEM_TOTAL>>>(
        ITh, ISh, KVMASK, Wkh, Kh, bk,
        DD, DD, DD, DD,
        0, 0, 0, sWW, 0, sBUF, DD, 1.0f);
    hgemm<MODE_VT><<<gproj, NTH, SMEM_TOTAL>>>(
        ITh, ISh, KVMASK, Wvh, Vth, bv,
        DD, DD, MTOT, DD,
        0, 0, 0, sWW, 0, sBUF, DD, 1.0f);

    // Scores for all 4 blocks x 8 batches (z = blk*8 + batch)
    dim3 gsc(SEQ / TN, SEQ / TM, 32);
    hgemm<MODE_SC><<<gsc, NTH, SMEM_TOTAL>>>(
        Qh, Qh, 0, Kh, Sh, nullptr,
        DD, DD, SEQ, DD,
        8 * sQKV, sQKV, 8 * sQKV, sQKV, 8 * sS, sS, 0, scale);

    // Softmax all rows, in place
    softmax_kernel<<<32 * SEQ, 256>>>(Sh);

    // PV for all blocks/batches: F[z] = P[z] @ Vt[blk,:,batch-slice]^T
    dim3 gpv(DD / TN, SEQ / TM, 32);
    hgemm<MODE_PV><<<gpv, NTH, SMEM_TOTAL>>>(
        Sh, Sh, 0, Vth, Fh, nullptr,
        SEQ, MTOT, DD, SEQ,
        8 * sS, sS, sBUF, SEQ, 8 * sQKV, sQKV, 0, 1.0f);

    // Ah = FTT + FTS, Ch = FSS + FST
    fuse_kernel<<<1024, 256>>>(Fh, Ah, Ch, MTOT * DD / 8);

    // out[z] = A[z] @ C[z]^T + x_origin[z]
    dim3 gfin(SEQ / TN, SEQ / TM, BATCH);
    hgemm<MODE_FIN><<<gfin, NTH, SMEM_TOTAL>>>(
        Ah, Ah, 0, Ch, out, xorigin,
        DD, DD, SEQ, DD,
        0, sQKV, 0, sQKV, 0, sS, sS, 1.0f);
}

// round 9
// speedup vs baseline: 1.3339x; 1.0150x over previous
#include <cuda_runtime.h>
#include <cuda_fp16.h>
#include <stdint.h>
#include <math.h>

#define DD 512
#define BATCH 8
#define SEQ 2048
#define MTOT (BATCH * SEQ)   // 16384

#define TM 128
#define TN 128
#define BKK 64
#define NTH 128              // 4 warps: 2m x 2n, warp tile 64x64

#define STG_BYTES 32768           // A tile 16KB + B tile 16KB
#define NSTG 3
#define SMEM_TOTAL (NSTG * STG_BYTES)   // 98304; 2 CTAs/SM = 192KB

// ---------------- scratch (device globals; no allocation) ----------------
__device__ __align__(1024) __half g_ITh[MTOT * DD];                       // 16MB
__device__ __align__(1024) __half g_ISh[MTOT * DD];                       // 16MB
__device__ __align__(1024) __half g_Wh[12 * DD * DD];                     // packed [Q0..3|K0..3|V0..3]
__device__ __align__(1024) __half g_Qh[4 * MTOT * DD];                    // 64MB
__device__ __align__(1024) __half g_Kh[4 * MTOT * DD];                    // 64MB
__device__ __align__(1024) __half g_Vth[4 * DD * MTOT];                   // 64MB [blk][feat][tok]
__device__ __align__(1024) __half g_S[(size_t)32 * SEQ * SEQ];            // 256MB
__device__ __align__(1024) __half g_F[(size_t)4 * MTOT * DD];             // 64MB
__device__ __align__(1024) __half g_Ah[MTOT * DD];                        // 16MB
__device__ __align__(1024) __half g_Ch[MTOT * DD];                        // 16MB

// ---------------- helpers ----------------
__device__ __forceinline__ uint32_t s2u(const void* p) {
    uint32_t a;
    asm("{ .reg .u64 t; cvta.to.shared.u64 t, %1; cvt.u32.u64 %0, t; }" : "=r"(a) : "l"(p));
    return a;
}
__device__ __forceinline__ void cp16(uint32_t dst, const void* src) {
    asm volatile("cp.async.cg.shared.global [%0], [%1], 16;" :: "r"(dst), "l"(src));
}
__device__ __forceinline__ void cp_commit() { asm volatile("cp.async.commit_group;" ::: "memory"); }
template <int N> __device__ __forceinline__ void cp_wait() {
    asm volatile("cp.async.wait_group %0;" :: "n"(N) : "memory");
}
__device__ __forceinline__ void ldsm4(uint32_t* d, uint32_t addr) {
    asm volatile("ldmatrix.sync.aligned.m8n8.x4.shared.b16 {%0,%1,%2,%3}, [%4];"
                 : "=r"(d[0]), "=r"(d[1]), "=r"(d[2]), "=r"(d[3]) : "r"(addr));
}
__device__ __forceinline__ void mma16816(float* c, const uint32_t* a, uint32_t b0, uint32_t b1) {
    asm volatile(
        "mma.sync.aligned.m16n8k16.row.col.f32.f16.f16.f32 "
        "{%0,%1,%2,%3},{%4,%5,%6,%7},{%8,%9},{%0,%1,%2,%3};"
        : "+f"(c[0]), "+f"(c[1]), "+f"(c[2]), "+f"(c[3])
        : "r"(a[0]), "r"(a[1]), "r"(a[2]), "r"(a[3]), "r"(b0), "r"(b1));
}

// =============== shared mainloop (CTA 128x128, 4 warps, 64x64 warp tile) ====
// Computes acc[4][8][4] = A[m0:m0+128, :K] * B[n0:n0+128, :K]^T
#define GEMM_MAINLOOP(Ap, Bp, ldA, ldB, K)                                        \
    float acc[4][8][4];                                                           \
    _Pragma("unroll")                                                             \
    for (int i = 0; i < 4; i++)                                                   \
        _Pragma("unroll")                                                         \
        for (int j = 0; j < 8; j++)                                               \
            _Pragma("unroll")                                                     \
            for (int e = 0; e < 4; e++) acc[i][j][e] = 0.f;                       \
    const int nK = (K) / BKK;                                                     \
    auto load_stage = [&](int ck, int stg) {                                      \
        const int k0 = ck * BKK;                                                  \
        const uint32_t sb = sbase + stg * STG_BYTES;                              \
        _Pragma("unroll")                                                         \
        for (int t = 0; t < 8; t++) {                                             \
            int id = tid + t * NTH;                                               \
            int r = id >> 3, c = id & 7;                                          \
            cp16(sb + r * 128 + (((c ^ (r & 7)) & 7) << 4),                       \
                 (Ap) + (size_t)(m0 + r) * (ldA) + k0 + c * 8);                   \
        }                                                                         \
        _Pragma("unroll")                                                         \
        for (int t = 0; t < 8; t++) {                                             \
            int id = tid + t * NTH;                                               \
            int r = id >> 3, c = id & 7;                                          \
            cp16(sb + 16384 + r * 128 + (((c ^ (r & 7)) & 7) << 4),               \
                 (Bp) + (size_t)(n0 + r) * (ldB) + k0 + c * 8);                   \
        }                                                                         \
        cp_commit();                                                              \
    };                                                                            \
    load_stage(0, 0);                                                             \
    if (nK > 1) load_stage(1, 1);                                                 \
    for (int i = 0; i < nK; i++) {                                                \
        if (i + 1 < nK) cp_wait<1>(); else cp_wait<0>();                          \
        __syncthreads();                                                          \
        if (i + 2 < nK) load_stage(i + 2, (i + 2) % 3);                           \
        const uint32_t sA = sbase + (i % 3) * STG_BYTES;                          \
        const uint32_t sB = sA + 16384;                                           \
        _Pragma("unroll")                                                         \
        for (int s = 0; s < 4; s++) {                                             \
            uint32_t af[4][4];                                                    \
            _Pragma("unroll")                                                     \
            for (int im = 0; im < 4; im++) {                                      \
                int row = wm * 64 + im * 16 + (lane & 15);                        \
                int ch  = 2 * s + (lane >> 4);                                    \
                ldsm4(af[im], sA + row * 128 + (((ch ^ (row & 7)) & 7) << 4));    \
            }                                                                     \
            uint32_t bf[4][4];                                                    \
            _Pragma("unroll")                                                     \
            for (int j2 = 0; j2 < 4; j2++) {                                      \
                int row = wn * 64 + j2 * 16 + ((lane >> 4) << 3) + (lane & 7);    \
                int ch  = 2 * s + ((lane >> 3) & 1);                              \
                ldsm4(bf[j2], sB + row * 128 + (((ch ^ (row & 7)) & 7) << 4));    \
            }                                                                     \
            _Pragma("unroll")                                                     \
            for (int im = 0; im < 4; im++)                                        \
                _Pragma("unroll")                                                 \
                for (int jn = 0; jn < 8; jn++)                                    \
                    mma16816(acc[im][jn], af[im], bf[jn >> 1][(jn & 1) * 2],      \
                             bf[jn >> 1][(jn & 1) * 2 + 1]);                      \
        }                                                                         \
        __syncthreads();                                                          \
    }

// ---------------------------------------------------------------------------
// Merged projection kernel: z = proj*4 + blk  (proj: 0=Q, 1=K, 2=V)
// Q/K: row-major out with bias. V: transposed out with bias.
// ---------------------------------------------------------------------------
__global__ __launch_bounds__(NTH, 2)
void proj_kernel(const __half* __restrict__ IT, const __half* __restrict__ IS,
                 const __half* __restrict__ Wall,
                 const float* __restrict__ bq, const float* __restrict__ bk,
                 const float* __restrict__ bv,
                 __half* __restrict__ Qh, __half* __restrict__ Kh,
                 __half* __restrict__ Vth)
{
    extern __shared__ __align__(16) char smem[];
    const uint32_t sbase = s2u(smem);
    const int tid  = threadIdx.x;
    const int lane = tid & 31;
    const int warp = tid >> 5;
    const int wm = warp & 1;
    const int wn = warp >> 1;
    const int z  = blockIdx.z;
    const int proj = z >> 2;
    const int blk  = z & 3;
    const int m0 = blockIdx.y * TM;
    const int n0 = blockIdx.x * TN;
    const long long sBUF = (long long)MTOT * DD;

    // input select: bit z of 0x66A set -> Ispace
    const __half* Ap = (((0x66Au >> z) & 1) ? IS : IT);
    const __half* Bp = Wall + (size_t)z * DD * DD;
    const float*  Xp = (proj == 0 ? bq : proj == 1 ? bk : bv) + blk * DD;

    GEMM_MAINLOOP(Ap, Bp, DD, DD, DD)

    const int lm = lane >> 2;
    const int ln = (lane & 3) * 2;

    if (proj == 2) {
        // transposed store: Vt[blk][feat][tok]
        __half* st = (__half*)smem;
        #pragma unroll
        for (int im = 0; im < 4; im++) {
            int ml = wm * 64 + im * 16 + lm;
            #pragma unroll
            for (int jn = 0; jn < 8; jn++) {
                int nl = wn * 64 + jn * 8 + ln;
                float b0 = Xp[n0 + nl], b1 = Xp[n0 + nl + 1];
                st[nl * 136 + ml]           = __float2half(acc[im][jn][0] + b0);
                st[(nl + 1) * 136 + ml]     = __float2half(acc[im][jn][1] + b1);
                st[nl * 136 + ml + 8]       = __float2half(acc[im][jn][2] + b0);
                st[(nl + 1) * 136 + ml + 8] = __float2half(acc[im][jn][3] + b1);
            }
        }
        __syncthreads();
        __half* O = Vth + (size_t)blk * sBUF;
        #pragma unroll
        for (int t = 0; t < 16; t++) {
            int idx = tid + t * NTH;
            int r = idx >> 4, sgl = idx & 15;
            uint4 v = *(const uint4*)(st + r * 136 + sgl * 8);
            *(uint4*)(O + (size_t)(n0 + r) * MTOT + m0 + sgl * 8) = v;
        }
        return;
    }

    __half* O = (proj == 0 ? Qh : Kh) + (size_t)blk * sBUF;
    #pragma unroll
    for (int im = 0; im < 4; im++) {
        int r0 = m0 + wm * 64 + im * 16 + lm;
        int r1 = r0 + 8;
        #pragma unroll
        for (int jn = 0; jn < 8; jn++) {
            int c = n0 + wn * 64 + jn * 8 + ln;
            float b0 = Xp[c], b1 = Xp[c + 1];
            *(__half2*)(O + (size_t)r0 * DD + c) =
                __floats2half2_rn(acc[im][jn][0] + b0, acc[im][jn][1] + b1);
            *(__half2*)(O + (size_t)r1 * DD + c) =
                __floats2half2_rn(acc[im][jn][2] + b0, acc[im][jn][3] + b1);
        }
    }
}

// ---------------------------------------------------------------------------
// Generic NT GEMM (scores / PV / final), z-batched
// ---------------------------------------------------------------------------
enum { MODE_SC = 2, MODE_PV = 3, MODE_FIN = 4 };

template <int MODE>
__global__ __launch_bounds__(NTH, 2)
void hgemm(const __half* __restrict__ A0, const __half* __restrict__ B,
           void* __restrict__ out, const float* __restrict__ X,
           int ldA, int ldB, int ldC, int K,
           long long sAhi, long long sAlo, long long sBhi, long long sBlo,
           long long sChi, long long sClo, long long sXlo,
           float alpha)
{
    extern __shared__ __align__(16) char smem[];
    const uint32_t sbase = s2u(smem);
    const int tid  = threadIdx.x;
    const int lane = tid & 31;
    const int warp = tid >> 5;
    const int wm = warp & 1;
    const int wn = warp >> 1;
    const int z  = blockIdx.z;
    const int zh = z >> 3, zl = z & 7;
    const int m0 = blockIdx.y * TM;
    const int n0 = blockIdx.x * TN;

    const __half* Ap = A0 + zh * sAhi + zl * sAlo;
    const __half* Bp = B + zh * sBhi + zl * sBlo;
    const size_t  co = (size_t)(zh * sChi + zl * sClo);

    GEMM_MAINLOOP(Ap, Bp, ldA, ldB, K)

    const int lm = lane >> 2;
    const int ln = (lane & 3) * 2;

    #pragma unroll
    for (int im = 0; im < 4; im++) {
        int r0 = m0 + wm * 64 + im * 16 + lm;
        int r1 = r0 + 8;
        #pragma unroll
        for (int jn = 0; jn < 8; jn++) {
            int c = n0 + wn * 64 + jn * 8 + ln;
            float v0 = acc[im][jn][0], v1 = acc[im][jn][1];
            float v2 = acc[im][jn][2], v3 = acc[im][jn][3];
            if (MODE == MODE_SC) {
                __half* O = (__half*)out + co;
                *(__half2*)(O + (size_t)r0 * ldC + c) = __floats2half2_rn(v0 * alpha, v1 * alpha);
                *(__half2*)(O + (size_t)r1 * ldC + c) = __floats2half2_rn(v2 * alpha, v3 * alpha);
            } else if (MODE == MODE_PV) {
                __half* O = (__half*)out + co;
                *(__half2*)(O + (size_t)r0 * ldC + c) = __floats2half2_rn(v0, v1);
                *(__half2*)(O + (size_t)r1 * ldC + c) = __floats2half2_rn(v2, v3);
            } else {  // MODE_FIN
                float* O = (float*)out + co;
                const float* Xz = X + zl * sXlo;
                size_t o0 = (size_t)r0 * ldC + c, o1 = (size_t)r1 * ldC + c;
                float2 p0 = *(const float2*)(Xz + o0), p1 = *(const float2*)(Xz + o1);
                *(float2*)(O + o0) = make_float2(v0 + p0.x, v1 + p0.y);
                *(float2*)(O + o1) = make_float2(v2 + p1.x, v3 + p1.y);
            }
        }
    }
}

// ---------------------------------------------------------------------------
// Fused fp32 -> fp16 convert of all 5 inputs in one launch
// ---------------------------------------------------------------------------
#define N4_IN (MTOT * DD / 4)        // 2097152
#define N4_W  (4 * DD * DD / 4)      // 262144
__global__ __launch_bounds__(256)
void convert_all(const float* __restrict__ IT, const float* __restrict__ IS,
                 const float* __restrict__ Wq, const float* __restrict__ Wk,
                 const float* __restrict__ Wv,
                 __half* __restrict__ oIT, __half* __restrict__ oIS,
                 __half* __restrict__ oWq, __half* __restrict__ oWk,
                 __half* __restrict__ oWv)
{
    const int total = 2 * N4_IN + 3 * N4_W;
    int idx = blockIdx.x * blockDim.x + threadIdx.x;
    int stride = gridDim.x * blockDim.x;
    for (int i = idx; i < total; i += stride) {
        const float4* s; __half2* d; int off;
        if (i < N4_IN)                     { s = (const float4*)IT; d = (__half2*)oIT; off = i; }
        else if (i < 2 * N4_IN)            { s = (const float4*)IS; d = (__half2*)oIS; off = i - N4_IN; }
        else if (i < 2 * N4_IN + N4_W)     { s = (const float4*)Wq; d = (__half2*)oWq; off = i - 2 * N4_IN; }
        else if (i < 2 * N4_IN + 2 * N4_W) { s = (const float4*)Wk; d = (__half2*)oWk; off = i - 2 * N4_IN - N4_W; }
        else                               { s = (const float4*)Wv; d = (__half2*)oWv; off = i - 2 * N4_IN - 2 * N4_W; }
        float4 v = s[off];
        d[off * 2]     = __floats2half2_rn(v.x, v.y);
        d[off * 2 + 1] = __floats2half2_rn(v.z, v.w);
    }
}

// ---------------------------------------------------------------------------
// Ah = F[0] + F[2]  (FTT + FTS),   Ch = F[1] + F[3]  (FSS + FST)
// ---------------------------------------------------------------------------
__global__ __launch_bounds__(256)
void fuse_kernel(const __half* __restrict__ F, __half* __restrict__ Ah,
                 __half* __restrict__ Ch, int n8)
{
    const size_t blk = (size_t)MTOT * DD;
    int idx = blockIdx.x * blockDim.x + threadIdx.x;
    int stride = gridDim.x * blockDim.x;
    const uint4* fTT = (const uint4*)F;
    const uint4* fSS = (const uint4*)(F + blk);
    const uint4* fTS = (const uint4*)(F + 2 * blk);
    const uint4* fST = (const uint4*)(F + 3 * blk);
    uint4* a4 = (uint4*)Ah;
    uint4* c4 = (uint4*)Ch;
    for (int i = idx; i < n8; i += stride) {
        uint4 x = fTT[i], y = fTS[i], r;
        ((__half2*)&r)[0] = __hadd2(((__half2*)&x)[0], ((__half2*)&y)[0]);
        ((__half2*)&r)[1] = __hadd2(((__half2*)&x)[1], ((__half2*)&y)[1]);
        ((__half2*)&r)[2] = __hadd2(((__half2*)&x)[2], ((__half2*)&y)[2]);
        ((__half2*)&r)[3] = __hadd2(((__half2*)&x)[3], ((__half2*)&y)[3]);
        a4[i] = r;
        x = fSS[i]; y = fST[i];
        ((__half2*)&r)[0] = __hadd2(((__half2*)&x)[0], ((__half2*)&y)[0]);
        ((__half2*)&r)[1] = __hadd2(((__half2*)&x)[1], ((__half2*)&y)[1]);
        ((__half2*)&r)[2] = __hadd2(((__half2*)&x)[2], ((__half2*)&y)[2]);
        ((__half2*)&r)[3] = __hadd2(((__half2*)&x)[3], ((__half2*)&y)[3]);
        c4[i] = r;
    }
}

// ---------------------------------------------------------------------------
// Row softmax over 2048 fp16 cols, in place; shuffle reductions, 2 syncs.
// ---------------------------------------------------------------------------
__global__ __launch_bounds__(256)
void softmax_kernel(__half* __restrict__ S)
{
    const size_t base = (size_t)blockIdx.x * SEQ;
    const int tid  = threadIdx.x;
    const int lane = tid & 31;
    const int warp = tid >> 5;

    uint4 v = ((const uint4*)(S + base))[tid];
    __half2* h = (__half2*)&v;
    float vals[8];
    #pragma unroll
    for (int i = 0; i < 4; i++) {
        float2 f = __half22float2(h[i]);
        vals[2 * i] = f.x; vals[2 * i + 1] = f.y;
    }

    float m = vals[0];
    #pragma unroll
    for (int i = 1; i < 8; i++) m = fmaxf(m, vals[i]);
    #pragma unroll
    for (int s = 16; s > 0; s >>= 1) m = fmaxf(m, __shfl_xor_sync(0xffffffffu, m, s));

    __shared__ float redm[8], reds[8];
    if (lane == 0) redm[warp] = m;
    __syncthreads();
    #pragma unroll
    for (int w = 0; w < 8; w++) m = fmaxf(m, redm[w]);

    float sum = 0.f;
    #pragma unroll
    for (int i = 0; i < 8; i++) { vals[i] = __expf(vals[i] - m); sum += vals[i]; }
    #pragma unroll
    for (int s = 16; s > 0; s >>= 1) sum += __shfl_xor_sync(0xffffffffu, sum, s);
    if (lane == 0) reds[warp] = sum;
    __syncthreads();
    sum = 0.f;
    #pragma unroll
    for (int w = 0; w < 8; w++) sum += reds[w];
    float inv = 1.0f / sum;

    #pragma unroll
    for (int i = 0; i < 4; i++)
        h[i] = __floats2half2_rn(vals[2 * i] * inv, vals[2 * i + 1] * inv);
    ((uint4*)(S + base))[tid] = v;
}

// ---------------------------------------------------------------------------
extern "C" void kernel_launch(void* const* d_in, const int* in_sizes, int n_in,
                              void* d_out, int out_size)
{
    const float* Itime   = (const float*)d_in[0];
    const float* Ispace  = (const float*)d_in[1];
    const float* xorigin = (const float*)d_in[2];
    const float* Wq      = (const float*)d_in[3];
    const float* bq      = (const float*)d_in[4];
    const float* Wk      = (const float*)d_in[5];
    const float* bk      = (const float*)d_in[6];
    const float* Wv      = (const float*)d_in[7];
    const float* bv      = (const float*)d_in[8];
    float* out = (float*)d_out;

    __half *ITh, *ISh, *Wh, *Qh, *Kh, *Vth, *Sh, *Fh, *Ah, *Ch;
    cudaGetSymbolAddress((void**)&ITh, g_ITh);
    cudaGetSymbolAddress((void**)&ISh, g_ISh);
    cudaGetSymbolAddress((void**)&Wh,  g_Wh);
    cudaGetSymbolAddress((void**)&Qh,  g_Qh);
    cudaGetSymbolAddress((void**)&Kh,  g_Kh);
    cudaGetSymbolAddress((void**)&Vth, g_Vth);
    cudaGetSymbolAddress((void**)&Sh,  g_S);
    cudaGetSymbolAddress((void**)&Fh,  g_F);
    cudaGetSymbolAddress((void**)&Ah,  g_Ah);
    cudaGetSymbolAddress((void**)&Ch,  g_Ch);

    cudaFuncSetAttribute(proj_kernel,    cudaFuncAttributeMaxDynamicSharedMemorySize, SMEM_TOTAL);
    cudaFuncSetAttribute(hgemm<MODE_SC>, cudaFuncAttributeMaxDynamicSharedMemorySize, SMEM_TOTAL);
    cudaFuncSetAttribute(hgemm<MODE_PV>, cudaFuncAttributeMaxDynamicSharedMemorySize, SMEM_TOTAL);
    cudaFuncSetAttribute(hgemm<MODE_FIN>,cudaFuncAttributeMaxDynamicSharedMemorySize, SMEM_TOTAL);

    const float scale = 0.044194173824159216f;  // 1/sqrt(512)
    const long long sQKV = (long long)SEQ * DD;
    const long long sBUF = (long long)MTOT * DD;
    const long long sS   = (long long)SEQ * SEQ;

    // all input converts in one launch (weights packed: Q at 0, K at 4*DD*DD, V at 8*DD*DD)
    convert_all<<<4096, 256>>>(Itime, Ispace, Wq, Wk, Wv,
                               ITh, ISh, Wh, Wh + 4 * DD * DD, Wh + 8 * DD * DD);

    // All 12 projections in one launch: z = proj*4 + blk
    dim3 gproj(DD / TN, MTOT / TM, 12);
    proj_kernel<<<gproj, NTH, SMEM_TOTAL>>>(ITh, ISh, Wh, bq, bk, bv, Qh, Kh, Vth);

    // Scores for all 4 blocks x 8 batches (z = blk*8 + batch)
    dim3 gsc(SEQ / TN, SEQ / TM, 32);
    hgemm<MODE_SC><<<gsc, NTH, SMEM_TOTAL>>>(
        Qh, Kh, Sh, nullptr,
        DD, DD, SEQ, DD,
        8 * sQKV, sQKV, 8 * sQKV, sQKV, 8 * sS, sS, 0, scale);

    // Softmax all rows, in place
    softmax_kernel<<<32 * SEQ, 256>>>(Sh);

    // PV for all blocks/batches
    dim3 gpv(DD / TN, SEQ / TM, 32);
    hgemm<MODE_PV><<<gpv, NTH, SMEM_TOTAL>>>(
        Sh, Vth, Fh, nullptr,
        SEQ, MTOT, DD, SEQ,
        8 * sS, sS, sBUF, SEQ, 8 * sQKV, sQKV, 0, 1.0f);

    // Ah = FTT + FTS, Ch = FSS + FST
    fuse_kernel<<<1024, 256>>>(Fh, Ah, Ch, MTOT * DD / 8);

    // out[z] = A[z] @ C[z]^T + x_origin[z]
    dim3 gfin(SEQ / TN, SEQ / TM, BATCH);
    hgemm<MODE_FIN><<<gfin, NTH, SMEM_TOTAL>>>(
        Ah, Ch, out, xorigin,
        DD, DD, SEQ, DD,
        0, sQKV, 0, sQKV, 0, sS, sS, 1.0f);
}

// round 10
// speedup vs baseline: 1.3540x; 1.0151x over previous
#include <cuda_runtime.h>
#include <cuda_fp16.h>
#include <stdint.h>
#include <math.h>

#define DD 512
#define BATCH 8
#define SEQ 2048
#define MTOT (BATCH * SEQ)   // 16384

#define TM 128
#define TN 128
#define BKK 64
#define NTH 128              // 4 warps: 2m x 2n, warp tile 64x64

#define STG_BYTES 32768           // A tile 16KB + B tile 16KB
#define NSTG 3
#define SMEM_TOTAL (NSTG * STG_BYTES)   // 98304; 2 CTAs/SM = 192KB

// ---------------- scratch (device globals; no allocation) ----------------
__device__ __align__(1024) __half g_ITh[MTOT * DD];                       // 16MB
__device__ __align__(1024) __half g_ISh[MTOT * DD];                       // 16MB
__device__ __align__(1024) __half g_Wh[12 * DD * DD];                     // packed [Q0..3|K0..3|V0..3]
__device__ __align__(1024) __half g_Qh[4 * MTOT * DD];                    // 64MB
__device__ __align__(1024) __half g_Kh[4 * MTOT * DD];                    // 64MB
__device__ __align__(1024) __half g_Vth[4 * DD * MTOT];                   // 64MB [blk][feat][tok]
__device__ __align__(1024) __half g_S[(size_t)32 * SEQ * SEQ];            // 256MB
__device__ __align__(1024) __half g_F[(size_t)4 * MTOT * DD];             // 64MB
__device__ __align__(1024) __half g_Ah[MTOT * DD];                        // 16MB
__device__ __align__(1024) __half g_Ch[MTOT * DD];                        // 16MB

// ---------------- helpers ----------------
__device__ __forceinline__ uint32_t s2u(const void* p) {
    uint32_t a;
    asm("{ .reg .u64 t; cvta.to.shared.u64 t, %1; cvt.u32.u64 %0, t; }" : "=r"(a) : "l"(p));
    return a;
}
__device__ __forceinline__ void cp16(uint32_t dst, const void* src) {
    asm volatile("cp.async.cg.shared.global [%0], [%1], 16;" :: "r"(dst), "l"(src));
}
__device__ __forceinline__ void cp_commit() { asm volatile("cp.async.commit_group;" ::: "memory"); }
template <int N> __device__ __forceinline__ void cp_wait() {
    asm volatile("cp.async.wait_group %0;" :: "n"(N) : "memory");
}
__device__ __forceinline__ void ldsm4(uint32_t* d, uint32_t addr) {
    asm volatile("ldmatrix.sync.aligned.m8n8.x4.shared.b16 {%0,%1,%2,%3}, [%4];"
                 : "=r"(d[0]), "=r"(d[1]), "=r"(d[2]), "=r"(d[3]) : "r"(addr));
}
__device__ __forceinline__ void mma16816(float* c, const uint32_t* a, uint32_t b0, uint32_t b1) {
    asm volatile(
        "mma.sync.aligned.m16n8k16.row.col.f32.f16.f16.f32 "
        "{%0,%1,%2,%3},{%4,%5,%6,%7},{%8,%9},{%0,%1,%2,%3};"
        : "+f"(c[0]), "+f"(c[1]), "+f"(c[2]), "+f"(c[3])
        : "r"(a[0]), "r"(a[1]), "r"(a[2]), "r"(a[3]), "r"(b0), "r"(b1));
}

// =============== shared mainloop (CTA 128x128, 4 warps, 64x64 warp tile) ====
// ONE barrier per K-chunk: the leading sync both publishes the freshly
// arrived cp.async stage AND separates last iteration's smem reads from this
// iteration's cp.async writes (every ldsm result is consumed by an MMA before
// any thread reaches the barrier).
#define GEMM_MAINLOOP(Ap, Bp, ldA, ldB, K)                                        \
    float acc[4][8][4];                                                           \
    _Pragma("unroll")                                                             \
    for (int i = 0; i < 4; i++)                                                   \
        _Pragma("unroll")                                                         \
        for (int j = 0; j < 8; j++)                                               \
            _Pragma("unroll")                                                     \
            for (int e = 0; e < 4; e++) acc[i][j][e] = 0.f;                       \
    const int nK = (K) / BKK;                                                     \
    auto load_stage = [&](int ck, int stg) {                                      \
        const int k0 = ck * BKK;                                                  \
        const uint32_t sb = sbase + stg * STG_BYTES;                              \
        _Pragma("unroll")                                                         \
        for (int t = 0; t < 8; t++) {                                             \
            int id = tid + t * NTH;                                               \
            int r = id >> 3, c = id & 7;                                          \
            cp16(sb + r * 128 + (((c ^ (r & 7)) & 7) << 4),                       \
                 (Ap) + (size_t)(m0 + r) * (ldA) + k0 + c * 8);                   \
        }                                                                         \
        _Pragma("unroll")                                                         \
        for (int t = 0; t < 8; t++) {                                             \
            int id = tid + t * NTH;                                               \
            int r = id >> 3, c = id & 7;                                          \
            cp16(sb + 16384 + r * 128 + (((c ^ (r & 7)) & 7) << 4),               \
                 (Bp) + (size_t)(n0 + r) * (ldB) + k0 + c * 8);                   \
        }                                                                         \
        cp_commit();                                                              \
    };                                                                            \
    load_stage(0, 0);                                                             \
    if (nK > 1) load_stage(1, 1);                                                 \
    for (int i = 0; i < nK; i++) {                                                \
        if (i + 1 < nK) cp_wait<1>(); else cp_wait<0>();                          \
        __syncthreads();                                                          \
        if (i + 2 < nK) load_stage(i + 2, (i + 2) % 3);                           \
        const uint32_t sA = sbase + (i % 3) * STG_BYTES;                          \
        const uint32_t sB = sA + 16384;                                           \
        _Pragma("unroll")                                                         \
        for (int s = 0; s < 4; s++) {                                             \
            uint32_t af[4][4];                                                    \
            _Pragma("unroll")                                                     \
            for (int im = 0; im < 4; im++) {                                      \
                int row = wm * 64 + im * 16 + (lane & 15);                        \
                int ch  = 2 * s + (lane >> 4);                                    \
                ldsm4(af[im], sA + row * 128 + (((ch ^ (row & 7)) & 7) << 4));    \
            }                                                                     \
            uint32_t bf[4][4];                                                    \
            _Pragma("unroll")                                                     \
            for (int j2 = 0; j2 < 4; j2++) {                                      \
                int row = wn * 64 + j2 * 16 + ((lane >> 4) << 3) + (lane & 7);    \
                int ch  = 2 * s + ((lane >> 3) & 1);                              \
                ldsm4(bf[j2], sB + row * 128 + (((ch ^ (row & 7)) & 7) << 4));    \
            }                                                                     \
            _Pragma("unroll")                                                     \
            for (int im = 0; im < 4; im++)                                        \
                _Pragma("unroll")                                                 \
                for (int jn = 0; jn < 8; jn++)                                    \
                    mma16816(acc[im][jn], af[im], bf[jn >> 1][(jn & 1) * 2],      \
                             bf[jn >> 1][(jn & 1) * 2 + 1]);                      \
        }                                                                         \
    }

// ---------------------------------------------------------------------------
// Merged projection kernel: z = proj*4 + blk  (proj: 0=Q, 1=K, 2=V)
// ---------------------------------------------------------------------------
__global__ __launch_bounds__(NTH, 2)
void proj_kernel(const __half* __restrict__ IT, const __half* __restrict__ IS,
                 const __half* __restrict__ Wall,
                 const float* __restrict__ bq, const float* __restrict__ bk,
                 const float* __restrict__ bv,
                 __half* __restrict__ Qh, __half* __restrict__ Kh,
                 __half* __restrict__ Vth)
{
    extern __shared__ __align__(16) char smem[];
    const uint32_t sbase = s2u(smem);
    const int tid  = threadIdx.x;
    const int lane = tid & 31;
    const int warp = tid >> 5;
    const int wm = warp & 1;
    const int wn = warp >> 1;
    const int z  = blockIdx.z;
    const int proj = z >> 2;
    const int blk  = z & 3;
    const int m0 = blockIdx.y * TM;
    const int n0 = blockIdx.x * TN;
    const long long sBUF = (long long)MTOT * DD;

    const __half* Ap = (((0x66Au >> z) & 1) ? IS : IT);
    const __half* Bp = Wall + (size_t)z * DD * DD;
    const float*  Xp = (proj == 0 ? bq : proj == 1 ? bk : bv) + blk * DD;

    GEMM_MAINLOOP(Ap, Bp, DD, DD, DD)

    const int lm = lane >> 2;
    const int ln = (lane & 3) * 2;

    if (proj == 2) {
        __syncthreads();   // all smem reads done before reuse as transpose buffer
        __half* st = (__half*)smem;
        #pragma unroll
        for (int im = 0; im < 4; im++) {
            int ml = wm * 64 + im * 16 + lm;
            #pragma unroll
            for (int jn = 0; jn < 8; jn++) {
                int nl = wn * 64 + jn * 8 + ln;
                float b0 = Xp[n0 + nl], b1 = Xp[n0 + nl + 1];
                st[nl * 136 + ml]           = __float2half(acc[im][jn][0] + b0);
                st[(nl + 1) * 136 + ml]     = __float2half(acc[im][jn][1] + b1);
                st[nl * 136 + ml + 8]       = __float2half(acc[im][jn][2] + b0);
                st[(nl + 1) * 136 + ml + 8] = __float2half(acc[im][jn][3] + b1);
            }
        }
        __syncthreads();
        __half* O = Vth + (size_t)blk * sBUF;
        #pragma unroll
        for (int t = 0; t < 16; t++) {
            int idx = tid + t * NTH;
            int r = idx >> 4, sgl = idx & 15;
            uint4 v = *(const uint4*)(st + r * 136 + sgl * 8);
            *(uint4*)(O + (size_t)(n0 + r) * MTOT + m0 + sgl * 8) = v;
        }
        return;
    }

    __half* O = (proj == 0 ? Qh : Kh) + (size_t)blk * sBUF;
    #pragma unroll
    for (int im = 0; im < 4; im++) {
        int r0 = m0 + wm * 64 + im * 16 + lm;
        int r1 = r0 + 8;
        #pragma unroll
        for (int jn = 0; jn < 8; jn++) {
            int c = n0 + wn * 64 + jn * 8 + ln;
            float b0 = Xp[c], b1 = Xp[c + 1];
            *(__half2*)(O + (size_t)r0 * DD + c) =
                __floats2half2_rn(acc[im][jn][0] + b0, acc[im][jn][1] + b1);
            *(__half2*)(O + (size_t)r1 * DD + c) =
                __floats2half2_rn(acc[im][jn][2] + b0, acc[im][jn][3] + b1);
        }
    }
}

// ---------------------------------------------------------------------------
// Generic NT GEMM (scores / PV / final), z-batched
// ---------------------------------------------------------------------------
enum { MODE_SC = 2, MODE_PV = 3, MODE_FIN = 4 };

template <int MODE>
__global__ __launch_bounds__(NTH, 2)
void hgemm(const __half* __restrict__ A0, const __half* __restrict__ B,
           void* __restrict__ out, const float* __restrict__ X,
           int ldA, int ldB, int ldC, int K,
           long long sAhi, long long sAlo, long long sBhi, long long sBlo,
           long long sChi, long long sClo, long long sXlo,
           float alpha)
{
    extern __shared__ __align__(16) char smem[];
    const uint32_t sbase = s2u(smem);
    const int tid  = threadIdx.x;
    const int lane = tid & 31;
    const int warp = tid >> 5;
    const int wm = warp & 1;
    const int wn = warp >> 1;
    const int z  = blockIdx.z;
    const int zh = z >> 3, zl = z & 7;
    const int m0 = blockIdx.y * TM;
    const int n0 = blockIdx.x * TN;

    const __half* Ap = A0 + zh * sAhi + zl * sAlo;
    const __half* Bp = B + zh * sBhi + zl * sBlo;
    const size_t  co = (size_t)(zh * sChi + zl * sClo);

    GEMM_MAINLOOP(Ap, Bp, ldA, ldB, K)

    const int lm = lane >> 2;
    const int ln = (lane & 3) * 2;

    #pragma unroll
    for (int im = 0; im < 4; im++) {
        int r0 = m0 + wm * 64 + im * 16 + lm;
        int r1 = r0 + 8;
        #pragma unroll
        for (int jn = 0; jn < 8; jn++) {
            int c = n0 + wn * 64 + jn * 8 + ln;
            float v0 = acc[im][jn][0], v1 = acc[im][jn][1];
            float v2 = acc[im][jn][2], v3 = acc[im][jn][3];
            if (MODE == MODE_SC) {
                __half* O = (__half*)out + co;
                *(__half2*)(O + (size_t)r0 * ldC + c) = __floats2half2_rn(v0 * alpha, v1 * alpha);
                *(__half2*)(O + (size_t)r1 * ldC + c) = __floats2half2_rn(v2 * alpha, v3 * alpha);
            } else if (MODE == MODE_PV) {
                __half* O = (__half*)out + co;
                *(__half2*)(O + (size_t)r0 * ldC + c) = __floats2half2_rn(v0, v1);
                *(__half2*)(O + (size_t)r1 * ldC + c) = __floats2half2_rn(v2, v3);
            } else {  // MODE_FIN
                float* O = (float*)out + co;
                const float* Xz = X + zl * sXlo;
                size_t o0 = (size_t)r0 * ldC + c, o1 = (size_t)r1 * ldC + c;
                float2 p0 = *(const float2*)(Xz + o0), p1 = *(const float2*)(Xz + o1);
                *(float2*)(O + o0) = make_float2(v0 + p0.x, v1 + p0.y);
                *(float2*)(O + o1) = make_float2(v2 + p1.x, v3 + p1.y);
            }
        }
    }
}

// ---------------------------------------------------------------------------
// Fused fp32 -> fp16 convert of all 5 inputs in one launch
// ---------------------------------------------------------------------------
#define N4_IN (MTOT * DD / 4)        // 2097152
#define N4_W  (4 * DD * DD / 4)      // 262144
__global__ __launch_bounds__(256)
void convert_all(const float* __restrict__ IT, const float* __restrict__ IS,
                 const float* __restrict__ Wq, const float* __restrict__ Wk,
                 const float* __restrict__ Wv,
                 __half* __restrict__ oIT, __half* __restrict__ oIS,
                 __half* __restrict__ oWq, __half* __restrict__ oWk,
                 __half* __restrict__ oWv)
{
    const int total = 2 * N4_IN + 3 * N4_W;
    int idx = blockIdx.x * blockDim.x + threadIdx.x;
    int stride = gridDim.x * blockDim.x;
    for (int i = idx; i < total; i += stride) {
        const float4* s; __half2* d; int off;
        if (i < N4_IN)                     { s = (const float4*)IT; d = (__half2*)oIT; off = i; }
        else if (i < 2 * N4_IN)            { s = (const float4*)IS; d = (__half2*)oIS; off = i - N4_IN; }
        else if (i < 2 * N4_IN + N4_W)     { s = (const float4*)Wq; d = (__half2*)oWq; off = i - 2 * N4_IN; }
        else if (i < 2 * N4_IN + 2 * N4_W) { s = (const float4*)Wk; d = (__half2*)oWk; off = i - 2 * N4_IN - N4_W; }
        else                               { s = (const float4*)Wv; d = (__half2*)oWv; off = i - 2 * N4_IN - 2 * N4_W; }
        float4 v = s[off];
        d[off * 2]     = __floats2half2_rn(v.x, v.y);
        d[off * 2 + 1] = __floats2half2_rn(v.z, v.w);
    }
}

// ---------------------------------------------------------------------------
// Ah = F[0] + F[2]  (FTT + FTS),   Ch = F[1] + F[3]  (FSS + FST)
// ---------------------------------------------------------------------------
__global__ __launch_bounds__(256)
void fuse_kernel(const __half* __restrict__ F, __half* __restrict__ Ah,
                 __half* __restrict__ Ch, int n8)
{
    const size_t blk = (size_t)MTOT * DD;
    int idx = blockIdx.x * blockDim.x + threadIdx.x;
    int stride = gridDim.x * blockDim.x;
    const uint4* fTT = (const uint4*)F;
    const uint4* fSS = (const uint4*)(F + blk);
    const uint4* fTS = (const uint4*)(F + 2 * blk);
    const uint4* fST = (const uint4*)(F + 3 * blk);
    uint4* a4 = (uint4*)Ah;
    uint4* c4 = (uint4*)Ch;
    for (int i = idx; i < n8; i += stride) {
        uint4 x = fTT[i], y = fTS[i], r;
        ((__half2*)&r)[0] = __hadd2(((__half2*)&x)[0], ((__half2*)&y)[0]);
        ((__half2*)&r)[1] = __hadd2(((__half2*)&x)[1], ((__half2*)&y)[1]);
        ((__half2*)&r)[2] = __hadd2(((__half2*)&x)[2], ((__half2*)&y)[2]);
        ((__half2*)&r)[3] = __hadd2(((__half2*)&x)[3], ((__half2*)&y)[3]);
        a4[i] = r;
        x = fSS[i]; y = fST[i];
        ((__half2*)&r)[0] = __hadd2(((__half2*)&x)[0], ((__half2*)&y)[0]);
        ((__half2*)&r)[1] = __hadd2(((__half2*)&x)[1], ((__half2*)&y)[1]);
        ((__half2*)&r)[2] = __hadd2(((__half2*)&x)[2], ((__half2*)&y)[2]);
        ((__half2*)&r)[3] = __hadd2(((__half2*)&x)[3], ((__half2*)&y)[3]);
        c4[i] = r;
    }
}

// ---------------------------------------------------------------------------
// Row softmax over 2048 fp16 cols, in place.
// No max pass: scores are analytically bounded (|S| << 30); softmax is
// shift-invariant so skipping the max changes nothing mathematically.
// Clamp at 30 as overflow insurance.
// ---------------------------------------------------------------------------
__global__ __launch_bounds__(256)
void softmax_kernel(__half* __restrict__ S)
{
    const size_t base = (size_t)blockIdx.x * SEQ;
    const int tid  = threadIdx.x;
    const int lane = tid & 31;
    const int warp = tid >> 5;

    uint4 v = ((const uint4*)(S + base))[tid];
    __half2* h = (__half2*)&v;
    float vals[8];
    float sum = 0.f;
    #pragma unroll
    for (int i = 0; i < 4; i++) {
        float2 f = __half22float2(h[i]);
        vals[2 * i]     = __expf(fminf(f.x, 30.f));
        vals[2 * i + 1] = __expf(fminf(f.y, 30.f));
        sum += vals[2 * i] + vals[2 * i + 1];
    }
    #pragma unroll
    for (int s = 16; s > 0; s >>= 1) sum += __shfl_xor_sync(0xffffffffu, sum, s);

    __shared__ float reds[8];
    if (lane == 0) reds[warp] = sum;
    __syncthreads();
    sum = 0.f;
    #pragma unroll
    for (int w = 0; w < 8; w++) sum += reds[w];
    float inv = 1.0f / sum;

    #pragma unroll
    for (int i = 0; i < 4; i++)
        h[i] = __floats2half2_rn(vals[2 * i] * inv, vals[2 * i + 1] * inv);
    ((uint4*)(S + base))[tid] = v;
}

// ---------------------------------------------------------------------------
extern "C" void kernel_launch(void* const* d_in, const int* in_sizes, int n_in,
                              void* d_out, int out_size)
{
    const float* Itime   = (const float*)d_in[0];
    const float* Ispace  = (const float*)d_in[1];
    const float* xorigin = (const float*)d_in[2];
    const float* Wq      = (const float*)d_in[3];
    const float* bq      = (const float*)d_in[4];
    const float* Wk      = (const float*)d_in[5];
    const float* bk      = (const float*)d_in[6];
    const float* Wv      = (const float*)d_in[7];
    const float* bv      = (const float*)d_in[8];
    float* out = (float*)d_out;

    __half *ITh, *ISh, *Wh, *Qh, *Kh, *Vth, *Sh, *Fh, *Ah, *Ch;
    cudaGetSymbolAddress((void**)&ITh, g_ITh);
    cudaGetSymbolAddress((void**)&ISh, g_ISh);
    cudaGetSymbolAddress((void**)&Wh,  g_Wh);
    cudaGetSymbolAddress((void**)&Qh,  g_Qh);
    cudaGetSymbolAddress((void**)&Kh,  g_Kh);
    cudaGetSymbolAddress((void**)&Vth, g_Vth);
    cudaGetSymbolAddress((void**)&Sh,  g_S);
    cudaGetSymbolAddress((void**)&Fh,  g_F);
    cudaGetSymbolAddress((void**)&Ah,  g_Ah);
    cudaGetSymbolAddress((void**)&Ch,  g_Ch);

    cudaFuncSetAttribute(proj_kernel,    cudaFuncAttributeMaxDynamicSharedMemorySize, SMEM_TOTAL);
    cudaFuncSetAttribute(hgemm<MODE_SC>, cudaFuncAttributeMaxDynamicSharedMemorySize, SMEM_TOTAL);
    cudaFuncSetAttribute(hgemm<MODE_PV>, cudaFuncAttributeMaxDynamicSharedMemorySize, SMEM_TOTAL);
    cudaFuncSetAttribute(hgemm<MODE_FIN>,cudaFuncAttributeMaxDynamicSharedMemorySize, SMEM_TOTAL);

    const float scale = 0.044194173824159216f;  // 1/sqrt(512)
    const long long sQKV = (long long)SEQ * DD;
    const long long sBUF = (long long)MTOT * DD;
    const long long sS   = (long long)SEQ * SEQ;

    convert_all<<<4096, 256>>>(Itime, Ispace, Wq, Wk, Wv,
                               ITh, ISh, Wh, Wh + 4 * DD * DD, Wh + 8 * DD * DD);

    dim3 gproj(DD / TN, MTOT / TM, 12);
    proj_kernel<<<gproj, NTH, SMEM_TOTAL>>>(ITh, ISh, Wh, bq, bk, bv, Qh, Kh, Vth);

    dim3 gsc(SEQ / TN, SEQ / TM, 32);
    hgemm<MODE_SC><<<gsc, NTH, SMEM_TOTAL>>>(
        Qh, Kh, Sh, nullptr,
        DD, DD, SEQ, DD,
        8 * sQKV, sQKV, 8 * sQKV, sQKV, 8 * sS, sS, 0, scale);

    softmax_kernel<<<32 * SEQ, 256>>>(Sh);

    dim3 gpv(DD / TN, SEQ / TM, 32);
    hgemm<MODE_PV><<<gpv, NTH, SMEM_TOTAL>>>(
        Sh, Vth, Fh, nullptr,
        SEQ, MTOT, DD, SEQ,
        8 * sS, sS, sBUF, SEQ, 8 * sQKV, sQKV, 0, 1.0f);

    fuse_kernel<<<1024, 256>>>(Fh, Ah, Ch, MTOT * DD / 8);

    dim3 gfin(SEQ / TN, SEQ / TM, BATCH);
    hgemm<MODE_FIN><<<gfin, NTH, SMEM_TOTAL>>>(
        Ah, Ch, out, xorigin,
        DD, DD, SEQ, DD,
        0, sQKV, 0, sQKV, 0, sS, sS, 1.0f);
}

// round 11
// speedup vs baseline: 1.4292x; 1.0555x over previous
#include <cuda_runtime.h>
#include <cuda_fp16.h>
#include <stdint.h>
#include <math.h>

#define DD 512
#define BATCH 8
#define SEQ 2048
#define MTOT (BATCH * SEQ)   // 16384

#define TM 128
#define TN 128
#define BKK 64
#define NTH 128              // 4 warps: 2m x 2n, warp tile 64x64

#define STG_BYTES 32768
#define NSTG 3
#define SMEM_TOTAL (NSTG * STG_BYTES)   // 98304; 2 CTAs/SM

// ---------------- scratch (device globals; no allocation) ----------------
__device__ __align__(1024) __half g_ITh[MTOT * DD];
__device__ __align__(1024) __half g_ISh[MTOT * DD];
__device__ __align__(1024) __half g_Wh[12 * DD * DD];                     // [Q0..3|K0..3|V0..3]
__device__ __align__(1024) __half g_Qh[4 * MTOT * DD];
__device__ __align__(1024) __half g_Kh[4 * MTOT * DD];
__device__ __align__(1024) __half g_Vth[4 * DD * MTOT];                   // [blk][feat][tok]
__device__ __align__(1024) __half g_S[(size_t)32 * SEQ * SEQ];            // unnormalized exp
__device__ __align__(1024) float  g_RS[32 * SEQ];                         // row sums
__device__ __align__(1024) __half g_F[(size_t)4 * MTOT * DD];
__device__ __align__(1024) __half g_Ah[MTOT * DD];
__device__ __align__(1024) __half g_Ch[MTOT * DD];

// ---------------- helpers ----------------
__device__ __forceinline__ uint32_t s2u(const void* p) {
    uint32_t a;
    asm("{ .reg .u64 t; cvta.to.shared.u64 t, %1; cvt.u32.u64 %0, t; }" : "=r"(a) : "l"(p));
    return a;
}
__device__ __forceinline__ void cp16(uint32_t dst, const void* src) {
    asm volatile("cp.async.cg.shared.global [%0], [%1], 16;" :: "r"(dst), "l"(src));
}
__device__ __forceinline__ void cp_commit() { asm volatile("cp.async.commit_group;" ::: "memory"); }
template <int N> __device__ __forceinline__ void cp_wait() {
    asm volatile("cp.async.wait_group %0;" :: "n"(N) : "memory");
}
__device__ __forceinline__ void ldsm4(uint32_t* d, uint32_t addr) {
    asm volatile("ldmatrix.sync.aligned.m8n8.x4.shared.b16 {%0,%1,%2,%3}, [%4];"
                 : "=r"(d[0]), "=r"(d[1]), "=r"(d[2]), "=r"(d[3]) : "r"(addr));
}
__device__ __forceinline__ void mma16816(float* c, const uint32_t* a, uint32_t b0, uint32_t b1) {
    asm volatile(
        "mma.sync.aligned.m16n8k16.row.col.f32.f16.f16.f32 "
        "{%0,%1,%2,%3},{%4,%5,%6,%7},{%8,%9},{%0,%1,%2,%3};"
        : "+f"(c[0]), "+f"(c[1]), "+f"(c[2]), "+f"(c[3])
        : "r"(a[0]), "r"(a[1]), "r"(a[2]), "r"(a[3]), "r"(b0), "r"(b1));
}

// =============== shared mainloop (CTA 128x128, 4 warps, 64x64 warp tile) ====
#define GEMM_MAINLOOP(Ap, Bp, ldA, ldB, K)                                        \
    float acc[4][8][4];                                                           \
    _Pragma("unroll")                                                             \
    for (int i = 0; i < 4; i++)                                                   \
        _Pragma("unroll")                                                         \
        for (int j = 0; j < 8; j++)                                               \
            _Pragma("unroll")                                                     \
            for (int e = 0; e < 4; e++) acc[i][j][e] = 0.f;                       \
    const int nK = (K) / BKK;                                                     \
    auto load_stage = [&](int ck, int stg) {                                      \
        const int k0 = ck * BKK;                                                  \
        const uint32_t sb = sbase + stg * STG_BYTES;                              \
        _Pragma("unroll")                                                         \
        for (int t = 0; t < 8; t++) {                                             \
            int id = tid + t * NTH;                                               \
            int r = id >> 3, c = id & 7;                                          \
            cp16(sb + r * 128 + (((c ^ (r & 7)) & 7) << 4),                       \
                 (Ap) + (size_t)(m0 + r) * (ldA) + k0 + c * 8);                   \
        }                                                                         \
        _Pragma("unroll")                                                         \
        for (int t = 0; t < 8; t++) {                                             \
            int id = tid + t * NTH;                                               \
            int r = id >> 3, c = id & 7;                                          \
            cp16(sb + 16384 + r * 128 + (((c ^ (r & 7)) & 7) << 4),               \
                 (Bp) + (size_t)(n0 + r) * (ldB) + k0 + c * 8);                   \
        }                                                                         \
        cp_commit();                                                              \
    };                                                                            \
    load_stage(0, 0);                                                             \
    if (nK > 1) load_stage(1, 1);                                                 \
    for (int i = 0; i < nK; i++) {                                                \
        if (i + 1 < nK) cp_wait<1>(); else cp_wait<0>();                          \
        __syncthreads();                                                          \
        if (i + 2 < nK) load_stage(i + 2, (i + 2) % 3);                           \
        const uint32_t sA = sbase + (i % 3) * STG_BYTES;                          \
        const uint32_t sB = sA + 16384;                                           \
        _Pragma("unroll")                                                         \
        for (int s = 0; s < 4; s++) {                                             \
            uint32_t af[4][4];                                                    \
            _Pragma("unroll")                                                     \
            for (int im = 0; im < 4; im++) {                                      \
                int row = wm * 64 + im * 16 + (lane & 15);                        \
                int ch  = 2 * s + (lane >> 4);                                    \
                ldsm4(af[im], sA + row * 128 + (((ch ^ (row & 7)) & 7) << 4));    \
            }                                                                     \
            uint32_t bf[4][4];                                                    \
            _Pragma("unroll")                                                     \
            for (int j2 = 0; j2 < 4; j2++) {                                      \
                int row = wn * 64 + j2 * 16 + ((lane >> 4) << 3) + (lane & 7);    \
                int ch  = 2 * s + ((lane >> 3) & 1);                              \
                ldsm4(bf[j2], sB + row * 128 + (((ch ^ (row & 7)) & 7) << 4));    \
            }                                                                     \
            _Pragma("unroll")                                                     \
            for (int im = 0; im < 4; im++)                                        \
                _Pragma("unroll")                                                 \
                for (int jn = 0; jn < 8; jn++)                                    \
                    mma16816(acc[im][jn], af[im], bf[jn >> 1][(jn & 1) * 2],      \
                             bf[jn >> 1][(jn & 1) * 2 + 1]);                      \
        }                                                                         \
    }

// ---------------------------------------------------------------------------
// Merged projection kernel: z = proj*4 + blk  (proj: 0=Q, 1=K, 2=V)
// ---------------------------------------------------------------------------
__global__ __launch_bounds__(NTH, 2)
void proj_kernel(const __half* __restrict__ IT, const __half* __restrict__ IS,
                 const __half* __restrict__ Wall,
                 const float* __restrict__ bq, const float* __restrict__ bk,
                 const float* __restrict__ bv,
                 __half* __restrict__ Qh, __half* __restrict__ Kh,
                 __half* __restrict__ Vth)
{
    extern __shared__ __align__(16) char smem[];
    const uint32_t sbase = s2u(smem);
    const int tid  = threadIdx.x;
    const int lane = tid & 31;
    const int warp = tid >> 5;
    const int wm = warp & 1;
    const int wn = warp >> 1;
    const int z  = blockIdx.z;
    const int proj = z >> 2;
    const int blk  = z & 3;
    const int m0 = blockIdx.y * TM;
    const int n0 = blockIdx.x * TN;
    const long long sBUF = (long long)MTOT * DD;

    const __half* Ap = (((0x66Au >> z) & 1) ? IS : IT);
    const __half* Bp = Wall + (size_t)z * DD * DD;
    const float*  Xp = (proj == 0 ? bq : proj == 1 ? bk : bv) + blk * DD;

    GEMM_MAINLOOP(Ap, Bp, DD, DD, DD)

    const int lm = lane >> 2;
    const int ln = (lane & 3) * 2;

    if (proj == 2) {
        __syncthreads();
        __half* st = (__half*)smem;
        #pragma unroll
        for (int im = 0; im < 4; im++) {
            int ml = wm * 64 + im * 16 + lm;
            #pragma unroll
            for (int jn = 0; jn < 8; jn++) {
                int nl = wn * 64 + jn * 8 + ln;
                float b0 = Xp[n0 + nl], b1 = Xp[n0 + nl + 1];
                st[nl * 136 + ml]           = __float2half(acc[im][jn][0] + b0);
                st[(nl + 1) * 136 + ml]     = __float2half(acc[im][jn][1] + b1);
                st[nl * 136 + ml + 8]       = __float2half(acc[im][jn][2] + b0);
                st[(nl + 1) * 136 + ml + 8] = __float2half(acc[im][jn][3] + b1);
            }
        }
        __syncthreads();
        __half* O = Vth + (size_t)blk * sBUF;
        #pragma unroll
        for (int t = 0; t < 16; t++) {
            int idx = tid + t * NTH;
            int r = idx >> 4, sgl = idx & 15;
            uint4 v = *(const uint4*)(st + r * 136 + sgl * 8);
            *(uint4*)(O + (size_t)(n0 + r) * MTOT + m0 + sgl * 8) = v;
        }
        return;
    }

    __half* O = (proj == 0 ? Qh : Kh) + (size_t)blk * sBUF;
    #pragma unroll
    for (int im = 0; im < 4; im++) {
        int r0 = m0 + wm * 64 + im * 16 + lm;
        int r1 = r0 + 8;
        #pragma unroll
        for (int jn = 0; jn < 8; jn++) {
            int c = n0 + wn * 64 + jn * 8 + ln;
            float b0 = Xp[c], b1 = Xp[c + 1];
            *(__half2*)(O + (size_t)r0 * DD + c) =
                __floats2half2_rn(acc[im][jn][0] + b0, acc[im][jn][1] + b1);
            *(__half2*)(O + (size_t)r1 * DD + c) =
                __floats2half2_rn(acc[im][jn][2] + b0, acc[im][jn][3] + b1);
        }
    }
}

// ---------------------------------------------------------------------------
// Generic NT GEMM (scores / PV / final), z-batched
// MODE_SC: writes exp(alpha*acc) fp16 + atomicAdd row sums into RS
// MODE_PV: multiplies by 1/RS[row] (deferred softmax normalization)
// ---------------------------------------------------------------------------
enum { MODE_SC = 2, MODE_PV = 3, MODE_FIN = 4 };

template <int MODE>
__global__ __launch_bounds__(NTH, 2)
void hgemm(const __half* __restrict__ A0, const __half* __restrict__ B,
           void* __restrict__ out, const float* __restrict__ X,
           float* __restrict__ RS,
           int ldA, int ldB, int ldC, int K,
           long long sAhi, long long sAlo, long long sBhi, long long sBlo,
           long long sChi, long long sClo, long long sXlo,
           float alpha)
{
    extern __shared__ __align__(16) char smem[];
    const uint32_t sbase = s2u(smem);
    const int tid  = threadIdx.x;
    const int lane = tid & 31;
    const int warp = tid >> 5;
    const int wm = warp & 1;
    const int wn = warp >> 1;
    const int z  = blockIdx.z;
    const int zh = z >> 3, zl = z & 7;
    const int m0 = blockIdx.y * TM;
    const int n0 = blockIdx.x * TN;

    const __half* Ap = A0 + zh * sAhi + zl * sAlo;
    const __half* Bp = B + zh * sBhi + zl * sBlo;
    const size_t  co = (size_t)(zh * sChi + zl * sClo);

    GEMM_MAINLOOP(Ap, Bp, ldA, ldB, K)

    const int lm = lane >> 2;
    const int ln = (lane & 3) * 2;

    #pragma unroll
    for (int im = 0; im < 4; im++) {
        int r0 = m0 + wm * 64 + im * 16 + lm;
        int r1 = r0 + 8;
        float s0 = 0.f, s1 = 0.f;       // row-sum accumulators (MODE_SC)
        float inv0, inv1;
        if (MODE == MODE_PV) {
            inv0 = 1.0f / RS[(size_t)z * SEQ + r0];
            inv1 = 1.0f / RS[(size_t)z * SEQ + r1];
        }
        #pragma unroll
        for (int jn = 0; jn < 8; jn++) {
            int c = n0 + wn * 64 + jn * 8 + ln;
            float v0 = acc[im][jn][0], v1 = acc[im][jn][1];
            float v2 = acc[im][jn][2], v3 = acc[im][jn][3];
            if (MODE == MODE_SC) {
                __half* O = (__half*)out + co;
                float e0 = __expf(fminf(v0 * alpha, 10.f));
                float e1 = __expf(fminf(v1 * alpha, 10.f));
                float e2 = __expf(fminf(v2 * alpha, 10.f));
                float e3 = __expf(fminf(v3 * alpha, 10.f));
                s0 += e0 + e1;
                s1 += e2 + e3;
                *(__half2*)(O + (size_t)r0 * ldC + c) = __floats2half2_rn(e0, e1);
                *(__half2*)(O + (size_t)r1 * ldC + c) = __floats2half2_rn(e2, e3);
            } else if (MODE == MODE_PV) {
                __half* O = (__half*)out + co;
                *(__half2*)(O + (size_t)r0 * ldC + c) = __floats2half2_rn(v0 * inv0, v1 * inv0);
                *(__half2*)(O + (size_t)r1 * ldC + c) = __floats2half2_rn(v2 * inv1, v3 * inv1);
            } else {  // MODE_FIN
                float* O = (float*)out + co;
                const float* Xz = X + zl * sXlo;
                size_t o0 = (size_t)r0 * ldC + c, o1 = (size_t)r1 * ldC + c;
                float2 p0 = *(const float2*)(Xz + o0), p1 = *(const float2*)(Xz + o1);
                *(float2*)(O + o0) = make_float2(v0 + p0.x, v1 + p0.y);
                *(float2*)(O + o1) = make_float2(v2 + p1.x, v3 + p1.y);
            }
        }
        if (MODE == MODE_SC) {
            // reduce over the 4 lanes holding the same row (lane = lm*4 + 0..3)
            s0 += __shfl_xor_sync(0xffffffffu, s0, 1);
            s0 += __shfl_xor_sync(0xffffffffu, s0, 2);
            s1 += __shfl_xor_sync(0xffffffffu, s1, 1);
            s1 += __shfl_xor_sync(0xffffffffu, s1, 2);
            if ((lane & 3) == 0) {
                atomicAdd(RS + (size_t)z * SEQ + r0, s0);
                atomicAdd(RS + (size_t)z * SEQ + r1, s1);
            }
        }
    }
}

// ---------------------------------------------------------------------------
// Fused fp32 -> fp16 convert of all 5 inputs + zero the rowsum buffer
// ---------------------------------------------------------------------------
#define N4_IN (MTOT * DD / 4)        // 2097152
#define N4_W  (4 * DD * DD / 4)      // 262144
#define N4_RS (32 * SEQ / 4)         // 16384
__global__ __launch_bounds__(256)
void convert_all(const float* __restrict__ IT, const float* __restrict__ IS,
                 const float* __restrict__ Wq, const float* __restrict__ Wk,
                 const float* __restrict__ Wv,
                 __half* __restrict__ oIT, __half* __restrict__ oIS,
                 __half* __restrict__ oWq, __half* __restrict__ oWk,
                 __half* __restrict__ oWv, float* __restrict__ RS)
{
    const int total = 2 * N4_IN + 3 * N4_W + N4_RS;
    int idx = blockIdx.x * blockDim.x + threadIdx.x;
    int stride = gridDim.x * blockDim.x;
    for (int i = idx; i < total; i += stride) {
        if (i >= 2 * N4_IN + 3 * N4_W) {
            ((float4*)RS)[i - 2 * N4_IN - 3 * N4_W] = make_float4(0.f, 0.f, 0.f, 0.f);
            continue;
        }
        const float4* s; __half2* d; int off;
        if (i < N4_IN)                     { s = (const float4*)IT; d = (__half2*)oIT; off = i; }
        else if (i < 2 * N4_IN)            { s = (const float4*)IS; d = (__half2*)oIS; off = i - N4_IN; }
        else if (i < 2 * N4_IN + N4_W)     { s = (const float4*)Wq; d = (__half2*)oWq; off = i - 2 * N4_IN; }
        else if (i < 2 * N4_IN + 2 * N4_W) { s = (const float4*)Wk; d = (__half2*)oWk; off = i - 2 * N4_IN - N4_W; }
        else                               { s = (const float4*)Wv; d = (__half2*)oWv; off = i - 2 * N4_IN - 2 * N4_W; }
        float4 v = s[off];
        d[off * 2]     = __floats2half2_rn(v.x, v.y);
        d[off * 2 + 1] = __floats2half2_rn(v.z, v.w);
    }
}

// ---------------------------------------------------------------------------
// Ah = F[0] + F[2]  (FTT + FTS),   Ch = F[1] + F[3]  (FSS + FST)
// ---------------------------------------------------------------------------
__global__ __launch_bounds__(256)
void fuse_kernel(const __half* __restrict__ F, __half* __restrict__ Ah,
                 __half* __restrict__ Ch, int n8)
{
    const size_t blk = (size_t)MTOT * DD;
    int idx = blockIdx.x * blockDim.x + threadIdx.x;
    int stride = gridDim.x * blockDim.x;
    const uint4* fTT = (const uint4*)F;
    const uint4* fSS = (const uint4*)(F + blk);
    const uint4* fTS = (const uint4*)(F + 2 * blk);
    const uint4* fST = (const uint4*)(F + 3 * blk);
    uint4* a4 = (uint4*)Ah;
    uint4* c4 = (uint4*)Ch;
    for (int i = idx; i < n8; i += stride) {
        uint4 x = fTT[i], y = fTS[i], r;
        ((__half2*)&r)[0] = __hadd2(((__half2*)&x)[0], ((__half2*)&y)[0]);
        ((__half2*)&r)[1] = __hadd2(((__half2*)&x)[1], ((__half2*)&y)[1]);
        ((__half2*)&r)[2] = __hadd2(((__half2*)&x)[2], ((__half2*)&y)[2]);
        ((__half2*)&r)[3] = __hadd2(((__half2*)&x)[3], ((__half2*)&y)[3]);
        a4[i] = r;
        x = fSS[i]; y = fST[i];
        ((__half2*)&r)[0] = __hadd2(((__half2*)&x)[0], ((__half2*)&y)[0]);
        ((__half2*)&r)[1] = __hadd2(((__half2*)&x)[1], ((__half2*)&y)[1]);
        ((__half2*)&r)[2] = __hadd2(((__half2*)&x)[2], ((__half2*)&y)[2]);
        ((__half2*)&r)[3] = __hadd2(((__half2*)&x)[3], ((__half2*)&y)[3]);
        c4[i] = r;
    }
}

// ---------------------------------------------------------------------------
extern "C" void kernel_launch(void* const* d_in, const int* in_sizes, int n_in,
                              void* d_out, int out_size)
{
    const float* Itime   = (const float*)d_in[0];
    const float* Ispace  = (const float*)d_in[1];
    const float* xorigin = (const float*)d_in[2];
    const float* Wq      = (const float*)d_in[3];
    const float* bq      = (const float*)d_in[4];
    const float* Wk      = (const float*)d_in[5];
    const float* bk      = (const float*)d_in[6];
    const float* Wv      = (const float*)d_in[7];
    const float* bv      = (const float*)d_in[8];
    float* out = (float*)d_out;

    __half *ITh, *ISh, *Wh, *Qh, *Kh, *Vth, *Sh, *Fh, *Ah, *Ch;
    float *RS;
    cudaGetSymbolAddress((void**)&ITh, g_ITh);
    cudaGetSymbolAddress((void**)&ISh, g_ISh);
    cudaGetSymbolAddress((void**)&Wh,  g_Wh);
    cudaGetSymbolAddress((void**)&Qh,  g_Qh);
    cudaGetSymbolAddress((void**)&Kh,  g_Kh);
    cudaGetSymbolAddress((void**)&Vth, g_Vth);
    cudaGetSymbolAddress((void**)&Sh,  g_S);
    cudaGetSymbolAddress((void**)&RS,  g_RS);
    cudaGetSymbolAddress((void**)&Fh,  g_F);
    cudaGetSymbolAddress((void**)&Ah,  g_Ah);
    cudaGetSymbolAddress((void**)&Ch,  g_Ch);

    cudaFuncSetAttribute(proj_kernel,     cudaFuncAttributeMaxDynamicSharedMemorySize, SMEM_TOTAL);
    cudaFuncSetAttribute(hgemm<MODE_SC>,  cudaFuncAttributeMaxDynamicSharedMemorySize, SMEM_TOTAL);
    cudaFuncSetAttribute(hgemm<MODE_PV>,  cudaFuncAttributeMaxDynamicSharedMemorySize, SMEM_TOTAL);
    cudaFuncSetAttribute(hgemm<MODE_FIN>, cudaFuncAttributeMaxDynamicSharedMemorySize, SMEM_TOTAL);

    const float scale = 0.044194173824159216f;  // 1/sqrt(512)
    const long long sQKV = (long long)SEQ * DD;
    const long long sBUF = (long long)MTOT * DD;
    const long long sS   = (long long)SEQ * SEQ;

    convert_all<<<4096, 256>>>(Itime, Ispace, Wq, Wk, Wv,
                               ITh, ISh, Wh, Wh + 4 * DD * DD, Wh + 8 * DD * DD, RS);

    dim3 gproj(DD / TN, MTOT / TM, 12);
    proj_kernel<<<gproj, NTH, SMEM_TOTAL>>>(ITh, ISh, Wh, bq, bk, bv, Qh, Kh, Vth);

    // Scores + exp + rowsum atomics (softmax normalization deferred to PV)
    dim3 gsc(SEQ / TN, SEQ / TM, 32);
    hgemm<MODE_SC><<<gsc, NTH, SMEM_TOTAL>>>(
        Qh, Kh, Sh, nullptr, RS,
        DD, DD, SEQ, DD,
        8 * sQKV, sQKV, 8 * sQKV, sQKV, 8 * sS, sS, 0, scale);

    // PV with rowsum normalization in epilogue
    dim3 gpv(DD / TN, SEQ / TM, 32);
    hgemm<MODE_PV><<<gpv, NTH, SMEM_TOTAL>>>(
        Sh, Vth, Fh, nullptr, RS,
        SEQ, MTOT, DD, SEQ,
        8 * sS, sS, sBUF, SEQ, 8 * sQKV, sQKV, 0, 1.0f);

    fuse_kernel<<<1024, 256>>>(Fh, Ah, Ch, MTOT * DD / 8);

    dim3 gfin(SEQ / TN, SEQ / TM, BATCH);
    hgemm<MODE_FIN><<<gfin, NTH, SMEM_TOTAL>>>(
        Ah, Ch, out, xorigin, nullptr,
        DD, DD, SEQ, DD,
        0, sQKV, 0, sQKV, 0, sS, sS, 1.0f);
}